// round 2
// baseline (speedup 1.0000x reference)
#include <cuda_runtime.h>
#include <math.h>

#define BB   32
#define CIN  32
#define HCC  64
#define HH   64
#define WW   64

// Tiling
#define TS   32        // spatial tile (32x32)
#define CB   4         // input-channel chunk
#define HG   4         // hidden channels per block
#define GCN  16        // gate channels per block = 4 gates * HG
#define IT   34        // input tile with halo
#define ITS  36        // padded smem row stride

__global__ __launch_bounds__(256, 2)
void convlstm_fp32_kernel(
    const float* __restrict__ x,
    const float* __restrict__ hs,
    const float* __restrict__ cs,
    const float* __restrict__ wxi, const float* __restrict__ wxf,
    const float* __restrict__ wxo, const float* __restrict__ wxg,
    const float* __restrict__ bxi, const float* __restrict__ bxf,
    const float* __restrict__ bxo, const float* __restrict__ bxg,
    const float* __restrict__ whi, const float* __restrict__ whf,
    const float* __restrict__ who, const float* __restrict__ whg,
    const float* __restrict__ bhi, const float* __restrict__ bhf,
    const float* __restrict__ bho, const float* __restrict__ bhg,
    float* __restrict__ hout, float* __restrict__ cout)
{
    __shared__ __align__(16) float in_s[CB][IT][ITS];
    __shared__ __align__(16) float w_s[CB][9][GCN];   // [ci][k][gate*4+j]

    const int tid  = threadIdx.x;
    const int b    = blockIdx.z;          // batch
    const int grp  = blockIdx.y;          // hidden group 0..15 (4 hc each)
    const int tile = blockIdx.x;          // 0..3 spatial tile
    const int ty0  = (tile >> 1) * TS;
    const int tx0  = (tile & 1) * TS;

    const int tyy = tid >> 4;             // 0..15
    const int txx = tid & 15;             // 0..15
    const int pyl = tyy * 2;              // local pixel base (within tile)
    const int pxl = txx * 2;

    const float* wx[4] = {wxi, wxf, wxo, wxg};
    const float* wh[4] = {whi, whf, who, whg};

    float acc[4][GCN];                    // [pixel 2x2][gate channel]
    #pragma unroll
    for (int p = 0; p < 4; p++)
        #pragma unroll
        for (int g = 0; g < GCN; g++)
            acc[p][g] = 0.0f;

    // Loop over all 96 "virtual" input channels: 0..31 = x, 32..95 = hidden
    for (int cc = 0; cc < CIN + HCC; cc += CB) {
        const bool isx = (cc < CIN);

        // --- cooperative input-tile load (with zero halo) ---
        for (int i = tid; i < CB * IT * IT; i += 256) {
            int ci  = i / (IT * IT);
            int rem = i - ci * IT * IT;
            int rr  = rem / IT;
            int ccx = rem - rr * IT;
            int gy = ty0 - 1 + rr;
            int gx = tx0 - 1 + ccx;
            float v = 0.0f;
            if ((unsigned)gy < HH && (unsigned)gx < WW) {
                if (isx) v = x [((b * CIN + (cc + ci))       * HH + gy) * WW + gx];
                else     v = hs[((b * HCC + (cc - CIN + ci)) * HH + gy) * WW + gx];
            }
            in_s[ci][rr][ccx] = v;
        }

        // --- cooperative weight-chunk load: w_s[ci][k][gate*4+j] ---
        for (int i = tid; i < CB * 9 * GCN; i += 256) {
            int gc = i & 15;
            int k  = (i >> 4) % 9;
            int ci = i / (9 * 16);
            int gate = gc >> 2;
            int j    = gc & 3;
            int hc   = grp * HG + j;
            float v;
            if (isx) v = wx[gate][(hc * CIN + cc + ci) * 9 + k];
            else     v = wh[gate][(hc * HCC + cc - CIN + ci) * 9 + k];
            w_s[ci][k][gc] = v;
        }
        __syncthreads();

        // --- register-blocked accumulation ---
        #pragma unroll
        for (int ci = 0; ci < CB; ci++) {
            float patch[4][4];
            #pragma unroll
            for (int r = 0; r < 4; r++)
                #pragma unroll
                for (int c = 0; c < 4; c++)
                    patch[r][c] = in_s[ci][pyl + r][pxl + c];

            #pragma unroll
            for (int ky = 0; ky < 3; ky++) {
                #pragma unroll
                for (int kx = 0; kx < 3; kx++) {
                    const float4* wp =
                        reinterpret_cast<const float4*>(&w_s[ci][ky * 3 + kx][0]);
                    float wv[GCN];
                    #pragma unroll
                    for (int q = 0; q < 4; q++) {
                        float4 t = wp[q];
                        wv[q * 4 + 0] = t.x; wv[q * 4 + 1] = t.y;
                        wv[q * 4 + 2] = t.z; wv[q * 4 + 3] = t.w;
                    }
                    float iv[4];
                    iv[0] = patch[ky    ][kx    ];
                    iv[1] = patch[ky    ][kx + 1];
                    iv[2] = patch[ky + 1][kx    ];
                    iv[3] = patch[ky + 1][kx + 1];
                    #pragma unroll
                    for (int p = 0; p < 4; p++)
                        #pragma unroll
                        for (int g = 0; g < GCN; g++)
                            acc[p][g] = fmaf(wv[g], iv[p], acc[p][g]);
                }
            }
        }
        __syncthreads();
    }

    // --- fused LSTM epilogue ---
    const int hcb = grp * HG;
    #pragma unroll
    for (int j = 0; j < HG; j++) {
        int hc = hcb + j;
        float bi = bxi[hc] + bhi[hc];
        float bf = bxf[hc] + bhf[hc];
        float bo = bxo[hc] + bho[hc];
        float bg = bxg[hc] + bhg[hc];
        #pragma unroll
        for (int p = 0; p < 4; p++) {
            int py = ty0 + pyl + (p >> 1);
            int px = tx0 + pxl + (p & 1);
            float zi = acc[p][0 * 4 + j] + bi;
            float zf = acc[p][1 * 4 + j] + bf;
            float zo = acc[p][2 * 4 + j] + bo;
            float zg = acc[p][3 * 4 + j] + bg;
            float ig = 1.0f / (1.0f + expf(-zi));
            float fg = 1.0f / (1.0f + expf(-zf));
            float og = 1.0f / (1.0f + expf(-zo));
            float gg = tanhf(zg);
            long idx = ((long)(b * HCC + hc) * HH + py) * WW + px;
            float cold = cs[idx];
            float cn = fg * cold + ig * gg;
            float hn = og * tanhf(cn);
            hout[idx] = hn;
            cout[idx] = cn;
        }
    }
}

extern "C" void kernel_launch(void* const* d_in, const int* in_sizes, int n_in,
                              void* d_out, int out_size)
{
    const float* x   = (const float*)d_in[0];
    const float* hs  = (const float*)d_in[1];
    const float* cs  = (const float*)d_in[2];

    // setup_inputs() builds the dict INTERLEAVED: w_xi, b_xi, w_xf, b_xf, ...,
    // w_hi, b_hi, ... Detect at runtime via element counts (bias = 64 elems).
    const float *WX[4], *BX[4], *WH[4], *BH[4];
    if (in_sizes[4] == HCC) {
        // interleaved: 3..10 = (w_x*, b_x*) x4 ; 11..18 = (w_h*, b_h*) x4
        for (int g = 0; g < 4; g++) {
            WX[g] = (const float*)d_in[3 + 2 * g];
            BX[g] = (const float*)d_in[4 + 2 * g];
            WH[g] = (const float*)d_in[11 + 2 * g];
            BH[g] = (const float*)d_in[12 + 2 * g];
        }
    } else {
        // grouped (reference-signature order)
        for (int g = 0; g < 4; g++) {
            WX[g] = (const float*)d_in[3 + g];
            BX[g] = (const float*)d_in[7 + g];
            WH[g] = (const float*)d_in[11 + g];
            BH[g] = (const float*)d_in[15 + g];
        }
    }

    float* hout = (float*)d_out;
    float* cout = hout + (long)BB * HCC * HH * WW;

    dim3 grid(4, 16, BB);   // 4 spatial tiles, 16 hidden groups, 32 batches
    dim3 block(256);
    convlstm_fp32_kernel<<<grid, block>>>(
        x, hs, cs,
        WX[0], WX[1], WX[2], WX[3], BX[0], BX[1], BX[2], BX[3],
        WH[0], WH[1], WH[2], WH[3], BH[0], BH[1], BH[2], BH[3],
        hout, cout);
}

// round 4
// speedup vs baseline: 3.3943x; 3.3943x over previous
#include <cuda_runtime.h>
#include <cstdint>

#define BB   32
#define CIN  32
#define HCC  64
#define HH   64
#define WW   64
#define CTOT 96          // 32 x-channels + 64 h-channels
#define NGATE 256        // 64 hc * 4 gates, packed n = hc*4 + gate
#define NITER 27         // 9 taps * 3 channel-chunks of 32

// ---------------- device scratch (static, allocation-free) ----------------
__device__ float g_A[(size_t)BB * HH * WW * CTOT];   // [b][y][x][c]  (tf32-rounded)
__device__ float g_W[NITER * NGATE * 32];            // [tap*3+kc][hc*4+gate][ci]
__device__ float g_bias[NGATE];                      // [hc*4+gate]

// ---------------- helpers ----------------
__device__ __forceinline__ float tf32_rn(float v) {
    uint32_t u;
    asm("cvt.rna.tf32.f32 %0, %1;" : "=r"(u) : "f"(v));
    return __uint_as_float(u);
}
__device__ __forceinline__ void cp_async16(uint32_t dst, const void* src, uint32_t sz) {
    asm volatile("cp.async.cg.shared.global [%0], [%1], 16, %2;"
                 :: "r"(dst), "l"(src), "r"(sz) : "memory");
}
__device__ __forceinline__ uint32_t smem_u32(const void* p) {
    uint32_t a;
    asm("{ .reg .u64 t; cvta.to.shared.u64 t, %1; cvt.u32.u64 %0, t; }" : "=r"(a) : "l"(p));
    return a;
}
#define CP_COMMIT() asm volatile("cp.async.commit_group;" ::: "memory")
#define CP_WAIT(n)  asm volatile("cp.async.wait_group %0;" :: "n"(n) : "memory")

__device__ __forceinline__ void mma_tf32(float* d, const uint32_t* a, const uint32_t* b) {
    asm volatile(
        "mma.sync.aligned.m16n8k8.row.col.f32.tf32.tf32.f32 "
        "{%0,%1,%2,%3}, {%4,%5,%6,%7}, {%8,%9}, {%0,%1,%2,%3};"
        : "+f"(d[0]), "+f"(d[1]), "+f"(d[2]), "+f"(d[3])
        : "r"(a[0]), "r"(a[1]), "r"(a[2]), "r"(a[3]), "r"(b[0]), "r"(b[1]));
}

__device__ __forceinline__ float fsigmoid(float v) {
    float e;
    asm("ex2.approx.f32 %0, %1;" : "=f"(e) : "f"(-v * 1.4426950408889634f));
    float r;
    asm("rcp.approx.f32 %0, %1;" : "=f"(r) : "f"(1.0f + e));
    return r;
}
__device__ __forceinline__ float ftanh(float v) {
    float e;
    asm("ex2.approx.f32 %0, %1;" : "=f"(e) : "f"(v * 2.885390081777927f));  // e^(2v)
    float r;
    asm("rcp.approx.f32 %0, %1;" : "=f"(r) : "f"(1.0f + e));
    return 1.0f - 2.0f * r;
}

// ---------------- pre-pass 1: NCHW x||h  ->  NHWC g_A (tf32-rounded) ----------------
__global__ __launch_bounds__(256) void pack_input(const float* __restrict__ x,
                                                  const float* __restrict__ hs) {
    __shared__ float sm[CTOT * 65];
    int b = blockIdx.x >> 6;
    int y = blockIdx.x & 63;
    int t = threadIdx.x;
    for (int idx = t; idx < CTOT * 64; idx += 256) {
        int c = idx >> 6, xp = idx & 63;
        float v;
        if (c < CIN) v = x[((size_t)(b * CIN + c) * HH + y) * WW + xp];
        else         v = hs[((size_t)(b * HCC + (c - CIN)) * HH + y) * WW + xp];
        sm[c * 65 + xp] = tf32_rn(v);
    }
    __syncthreads();
    float* dst = g_A + (size_t)(b * HH + y) * WW * CTOT;
    for (int o = t; o < CTOT * 64; o += 256) {
        int xp = o / CTOT, c = o - xp * CTOT;
        dst[o] = sm[c * 65 + xp];
    }
}

// ---------------- pre-pass 2: weights -> g_W [tap*3+kc][hc*4+gate][32] -------------
__global__ __launch_bounds__(256) void pack_weights(
    const float* wxi, const float* wxf, const float* wxo, const float* wxg,
    const float* whi, const float* whf, const float* who, const float* whg,
    const float* bxi, const float* bxf, const float* bxo, const float* bxg,
    const float* bhi, const float* bhf, const float* bho, const float* bhg) {
    const float* wx[4] = {wxi, wxf, wxo, wxg};
    const float* wh[4] = {whi, whf, who, whg};
    int g = blockIdx.x * 256 + threadIdx.x;
    if (g < NITER * NGATE * 32) {
        int ci = g & 31;
        int r = g >> 5;
        int n = r & 255;
        int tk = r >> 8;              // tap*3 + kc
        int tap = tk / 3, kc = tk - 3 * tap;
        int ky = tap / 3, kx = tap - 3 * ky;
        int hc = n >> 2, gate = n & 3;
        int cg = kc * 32 + ci;
        float v;
        if (cg < CIN) v = wx[gate][((hc * CIN + cg) * 3 + ky) * 3 + kx];
        else          v = wh[gate][((hc * HCC + (cg - CIN)) * 3 + ky) * 3 + kx];
        g_W[g] = tf32_rn(v);
    }
    if (blockIdx.x == 0) {
        const float* bx[4] = {bxi, bxf, bxo, bxg};
        const float* bh[4] = {bhi, bhf, bho, bhg};
        int t = threadIdx.x;          // n = hc*4+gate
        int hc = t >> 2, gate = t & 3;
        g_bias[t] = bx[gate][hc] + bh[gate][hc];
    }
}

// ---------------- main mma.sync kernel ----------------
// smem (floats): A stage: 128 rows x 36 (pad)  = 4608 f (18432 B)
//                B stage: 256 rows x 36 (pad)  = 9216 f (36864 B)
#define A_STRIDE 36
#define A_STAGE_F 4608
#define B_STAGE_F 9216
#define SMEM_FLOATS (2 * A_STAGE_F + 2 * B_STAGE_F)
#define SMEM_BYTES  (SMEM_FLOATS * 4)   // 110592

__global__ __launch_bounds__(512, 1) void convlstm_mma(
    const float* __restrict__ cs, float* __restrict__ hout, float* __restrict__ cout) {
    extern __shared__ float smf[];
    const uint32_t sb = smem_u32(smf);
    const int tid  = threadIdx.x;
    const int wid  = tid >> 5;
    const int lane = tid & 31;
    const int gid  = lane >> 2;        // groupID
    const int tig  = lane & 3;         // thread-in-group
    const int warp_m = (wid >> 3) * 64;
    const int warp_n = (wid & 7) * 32;

    const int b  = blockIdx.x >> 5;
    const int y0 = (blockIdx.x & 31) * 2;
    const float* Ab = g_A + (size_t)b * HH * WW * CTOT;

    float acc[4][4][4];
    #pragma unroll
    for (int mi = 0; mi < 4; mi++)
        #pragma unroll
        for (int ni = 0; ni < 4; ni++)
            #pragma unroll
            for (int q = 0; q < 4; q++) acc[mi][ni][q] = 0.0f;

    // ---- async tile loader for iteration `it` into stage s ----
    auto prefetch = [&](int it, int s) {
        const int tap = it / 3, kc = it - 3 * tap;
        const int ky = tap / 3, kx = tap - 3 * ky;
        const uint32_t a_base = sb + (uint32_t)(s * A_STAGE_F) * 4;
        const uint32_t b_base = sb + (uint32_t)((2 * A_STAGE_F + s * B_STAGE_F)) * 4;
        // A: 128 rows x 8 chunks of 16B
        #pragma unroll
        for (int u = 0; u < 2; u++) {
            int c = tid + u * 512;
            int r = c >> 3, j = c & 7;
            int xi = (r & 63) + kx - 1;
            int yi = y0 + (r >> 6) + ky - 1;
            bool ok = ((unsigned)xi < WW) && ((unsigned)yi < HH);
            const float* src = ok ? (Ab + ((size_t)(yi * WW + xi)) * CTOT + kc * 32 + j * 4)
                                  : Ab;
            cp_async16(a_base + (uint32_t)(r * A_STRIDE * 4 + j * 16), src, ok ? 16u : 0u);
        }
        // B: 256 rows x 8 chunks of 16B
        const float* Wsrc = g_W + (size_t)it * NGATE * 32;
        #pragma unroll
        for (int u = 0; u < 4; u++) {
            int c = tid + u * 512;
            int r = c >> 3, j = c & 7;
            cp_async16(b_base + (uint32_t)(r * A_STRIDE * 4 + j * 16),
                       Wsrc + r * 32 + j * 4, 16u);
        }
        CP_COMMIT();
    };

    prefetch(0, 0);
    for (int it = 0; it < NITER; it++) {
        const int s = it & 1;
        if (it + 1 < NITER) prefetch(it + 1, s ^ 1);
        if (it + 1 < NITER) { CP_WAIT(1); } else { CP_WAIT(0); }
        __syncthreads();

        const float* As_ = smf + s * A_STAGE_F;
        const float* Bs_ = smf + 2 * A_STAGE_F + s * B_STAGE_F;

        #pragma unroll
        for (int ks = 0; ks < 4; ks++) {
            const int k0 = ks * 8;
            uint32_t af[4][4];
            #pragma unroll
            for (int mi = 0; mi < 4; mi++) {
                const float* ap = As_ + (warp_m + mi * 16 + gid) * A_STRIDE + k0 + tig;
                af[mi][0] = __float_as_uint(ap[0]);
                af[mi][1] = __float_as_uint(ap[8 * A_STRIDE]);
                af[mi][2] = __float_as_uint(ap[4]);
                af[mi][3] = __float_as_uint(ap[8 * A_STRIDE + 4]);
            }
            uint32_t bf[4][2];
            #pragma unroll
            for (int ni = 0; ni < 4; ni++) {
                const float* bp = Bs_ + (warp_n + ni * 8 + gid) * A_STRIDE + k0 + tig;
                bf[ni][0] = __float_as_uint(bp[0]);
                bf[ni][1] = __float_as_uint(bp[4]);
            }
            #pragma unroll
            for (int mi = 0; mi < 4; mi++)
                #pragma unroll
                for (int ni = 0; ni < 4; ni++)
                    mma_tf32(acc[mi][ni], af[mi], bf[ni]);
        }
        __syncthreads();
    }

    // ---- fused LSTM epilogue, all in registers via lane-pair shfl ----
    // col(n) = warp_n + ni*8 + tig*2 + {0,1}; n = hc*4 + gate
    //   even tig-pair lane: cols are gates {0,1}(=i,f); odd: gates {2,3}(=o,g)
    // row = warp_m + mi*16 + gid (+8 for c2,c3)
    const int odd = tig & 1;
    #pragma unroll
    for (int mi = 0; mi < 4; mi++) {
        #pragma unroll
        for (int ni = 0; ni < 4; ni++) {
            float c0 = acc[mi][ni][0], c1 = acc[mi][ni][1];
            float c2 = acc[mi][ni][2], c3 = acc[mi][ni][3];
            // even lane keeps row r (needs peer's c0,c1 = zo,zg of row r)
            // odd  lane keeps row r+8 (needs peer's c2,c3 = zi,zf of row r+8)
            float e0 = __shfl_xor_sync(0xFFFFFFFFu, odd ? c0 : c2, 1);
            float e1 = __shfl_xor_sync(0xFFFFFFFFu, odd ? c1 : c3, 1);
            float zi, zf, zo, zg;
            int row;
            if (!odd) { zi = c0; zf = c1; zo = e0; zg = e1; row = warp_m + mi * 16 + gid; }
            else      { zi = e0; zf = e1; zo = c2; zg = c3; row = warp_m + mi * 16 + gid + 8; }
            const int hc = (warp_n >> 2) + ni * 2 + (tig >> 1);
            const float4 bv = *(const float4*)(g_bias + hc * 4);
            zi += bv.x; zf += bv.y; zo += bv.z; zg += bv.w;

            float ig = fsigmoid(zi), fg = fsigmoid(zf), og = fsigmoid(zo);
            float gg = ftanh(zg);
            const int y = y0 + (row >> 6);
            const int x = row & 63;
            size_t cidx = ((size_t)(b * HCC + hc) * HH + y) * WW + x;
            float cn = fg * cs[cidx] + ig * gg;
            hout[cidx] = og * ftanh(cn);
            cout[cidx] = cn;
        }
    }
}

// ---------------- host ----------------
extern "C" void kernel_launch(void* const* d_in, const int* in_sizes, int n_in,
                              void* d_out, int out_size) {
    const float* x  = (const float*)d_in[0];
    const float* hs = (const float*)d_in[1];
    const float* cs = (const float*)d_in[2];

    const float *WX[4], *BX[4], *WH[4], *BH[4];
    if (in_sizes[4] == HCC) {           // interleaved: w_xi,b_xi,w_xf,b_xf,...
        for (int g = 0; g < 4; g++) {
            WX[g] = (const float*)d_in[3 + 2 * g];
            BX[g] = (const float*)d_in[4 + 2 * g];
            WH[g] = (const float*)d_in[11 + 2 * g];
            BH[g] = (const float*)d_in[12 + 2 * g];
        }
    } else {                            // grouped
        for (int g = 0; g < 4; g++) {
            WX[g] = (const float*)d_in[3 + g];
            BX[g] = (const float*)d_in[7 + g];
            WH[g] = (const float*)d_in[11 + g];
            BH[g] = (const float*)d_in[15 + g];
        }
    }

    float* hout = (float*)d_out;
    float* cout = hout + (size_t)BB * HCC * HH * WW;

    pack_input<<<BB * HH, 256>>>(x, hs);
    pack_weights<<<(NITER * NGATE * 32 + 255) / 256, 256>>>(
        WX[0], WX[1], WX[2], WX[3], WH[0], WH[1], WH[2], WH[3],
        BX[0], BX[1], BX[2], BX[3], BH[0], BH[1], BH[2], BH[3]);

    cudaFuncSetAttribute(convlstm_mma, cudaFuncAttributeMaxDynamicSharedMemorySize, SMEM_BYTES);
    convlstm_mma<<<1024, 512, SMEM_BYTES>>>(cs, hout, cout);
}

// round 5
// speedup vs baseline: 3.6332x; 1.0704x over previous
#include <cuda_runtime.h>
#include <cstdint>

#define BB   32
#define CIN  32
#define HCC  64
#define HH   64
#define WW   64
#define CTOT 96          // 32 x-channels + 64 h-channels
#define NGATE 256        // 64 hc * 4 gates, packed n = hc*4 + gate
#define NITER 27         // 9 taps * 3 channel-chunks of 32

// ---------------- device scratch (static, allocation-free) ----------------
__device__ float g_A[(size_t)BB * HH * WW * CTOT];   // [b][y][x][c'] perm-channel, tf32
__device__ float g_W[NITER * NGATE * 32];            // [tap*3+kc][hc*4+gate][ci'] perm
__device__ float g_bias[NGATE];                      // [hc*4+gate]

// ---------------- helpers ----------------
__device__ __forceinline__ float tf32_rn(float v) {
    uint32_t u;
    asm("cvt.rna.tf32.f32 %0, %1;" : "=r"(u) : "f"(v));
    return __uint_as_float(u);
}
__device__ __forceinline__ void cp_async16(uint32_t dst, const void* src, uint32_t sz) {
    asm volatile("cp.async.cg.shared.global [%0], [%1], 16, %2;"
                 :: "r"(dst), "l"(src), "r"(sz) : "memory");
}
__device__ __forceinline__ uint32_t smem_u32(const void* p) {
    uint32_t a;
    asm("{ .reg .u64 t; cvta.to.shared.u64 t, %1; cvt.u32.u64 %0, t; }" : "=r"(a) : "l"(p));
    return a;
}
#define CP_COMMIT() asm volatile("cp.async.commit_group;" ::: "memory")
#define CP_WAIT(n)  asm volatile("cp.async.wait_group %0;" :: "n"(n) : "memory")

__device__ __forceinline__ void mma_tf32(float* d, uint32_t a0, uint32_t a1, uint32_t a2,
                                         uint32_t a3, uint32_t b0, uint32_t b1) {
    asm volatile(
        "mma.sync.aligned.m16n8k8.row.col.f32.tf32.tf32.f32 "
        "{%0,%1,%2,%3}, {%4,%5,%6,%7}, {%8,%9}, {%0,%1,%2,%3};"
        : "+f"(d[0]), "+f"(d[1]), "+f"(d[2]), "+f"(d[3])
        : "r"(a0), "r"(a1), "r"(a2), "r"(a3), "r"(b0), "r"(b1));
}

__device__ __forceinline__ float fsigmoid(float v) {
    float e;
    asm("ex2.approx.f32 %0, %1;" : "=f"(e) : "f"(-v * 1.4426950408889634f));
    float r;
    asm("rcp.approx.f32 %0, %1;" : "=f"(r) : "f"(1.0f + e));
    return r;
}
__device__ __forceinline__ float ftanh(float v) {
    float e;
    asm("ex2.approx.f32 %0, %1;" : "=f"(e) : "f"(v * 2.885390081777927f));  // e^(2v)
    float r;
    asm("rcp.approx.f32 %0, %1;" : "=f"(r) : "f"(1.0f + e));
    return 1.0f - 2.0f * r;
}

// inverse of channel-pair permutation (within 8-block):
// stored pos p -> original local channel (p>>1) + (p&1)*4
__device__ __forceinline__ int inv_perm8(int p) { return (p >> 1) + ((p & 1) << 2); }

// ---------------- pre-pass 1: NCHW x||h -> NHWC g_A (tf32, perm channels) ----------
__global__ __launch_bounds__(256) void pack_input(const float* __restrict__ x,
                                                  const float* __restrict__ hs) {
    __shared__ float sm[CTOT * 65];
    int b = blockIdx.x >> 6;
    int y = blockIdx.x & 63;
    int t = threadIdx.x;
    for (int idx = t; idx < CTOT * 64; idx += 256) {
        int c = idx >> 6, xp = idx & 63;
        float v;
        if (c < CIN) v = x[((size_t)(b * CIN + c) * HH + y) * WW + xp];
        else         v = hs[((size_t)(b * HCC + (c - CIN)) * HH + y) * WW + xp];
        sm[c * 65 + xp] = tf32_rn(v);
    }
    __syncthreads();
    float* dst = g_A + (size_t)(b * HH + y) * WW * CTOT;
    for (int o = t; o < CTOT * 64; o += 256) {
        int xp = o / CTOT, cpos = o - xp * CTOT;
        int c = (cpos & ~7) | inv_perm8(cpos & 7);
        dst[o] = sm[c * 65 + xp];
    }
}

// ---------------- pre-pass 2: weights -> g_W [tap*3+kc][hc*4+gate][ci'] ------------
__global__ __launch_bounds__(256) void pack_weights(
    const float* wxi, const float* wxf, const float* wxo, const float* wxg,
    const float* whi, const float* whf, const float* who, const float* whg,
    const float* bxi, const float* bxf, const float* bxo, const float* bxg,
    const float* bhi, const float* bhf, const float* bho, const float* bhg) {
    const float* wx[4] = {wxi, wxf, wxo, wxg};
    const float* wh[4] = {whi, whf, who, whg};
    int g = blockIdx.x * 256 + threadIdx.x;
    if (g < NITER * NGATE * 32) {
        int ci = g & 31;                          // stored position
        int r = g >> 5;
        int n = r & 255;
        int tk = r >> 8;                          // tap*3 + kc
        int tap = tk / 3, kc = tk - 3 * tap;
        int ky = tap / 3, kx = tap - 3 * ky;
        int hc = n >> 2, gate = n & 3;
        int cg = kc * 32 + (ci & 24) + inv_perm8(ci & 7);   // original channel
        float v;
        if (cg < CIN) v = wx[gate][((hc * CIN + cg) * 3 + ky) * 3 + kx];
        else          v = wh[gate][((hc * HCC + (cg - CIN)) * 3 + ky) * 3 + kx];
        g_W[g] = tf32_rn(v);
    }
    if (blockIdx.x == 0) {
        const float* bx[4] = {bxi, bxf, bxo, bxg};
        const float* bh[4] = {bhi, bhf, bho, bhg};
        int t = threadIdx.x;          // n = hc*4+gate
        int hc = t >> 2, gate = t & 3;
        g_bias[t] = bx[gate][hc] + bh[gate][hc];
    }
}

// ---------------- main mma.sync kernel ----------------
#define A_STRIDE 40
#define A_STAGE_F (128 * A_STRIDE)            // 5120 floats
#define B_STAGE_F (256 * A_STRIDE)            // 10240 floats
#define STAGE_F   (A_STAGE_F + B_STAGE_F)     // 15360 floats
#define NSTAGE 3
#define SMEM_BYTES (NSTAGE * STAGE_F * 4)     // 184320

__global__ __launch_bounds__(256, 1) void convlstm_mma(
    const float* __restrict__ cs, float* __restrict__ hout, float* __restrict__ cout) {
    extern __shared__ float smf[];
    const uint32_t sb = smem_u32(smf);
    const int tid  = threadIdx.x;
    const int wid  = tid >> 5;
    const int lane = tid & 31;
    const int gid  = lane >> 2;        // groupID 0..7
    const int tig  = lane & 3;         // thread-in-group
    const int warp_m = (wid >> 2) * 64;   // 2 warps over M
    const int warp_n = (wid & 3) * 64;    // 4 warps over N

    const int b  = blockIdx.x >> 5;
    const int y0 = (blockIdx.x & 31) * 2;
    const float* Ab = g_A + (size_t)b * HH * WW * CTOT;

    float acc[4][8][4];
    #pragma unroll
    for (int mi = 0; mi < 4; mi++)
        #pragma unroll
        for (int ni = 0; ni < 8; ni++)
            #pragma unroll
            for (int q = 0; q < 4; q++) acc[mi][ni][q] = 0.0f;

    // ---- async tile loader for iteration `it` into stage s ----
    auto prefetch = [&](int it, int s) {
        const int tap = it / 3, kc = it - 3 * tap;
        const int ky = tap / 3, kx = tap - 3 * ky;
        const uint32_t st_base = sb + (uint32_t)(s * STAGE_F) * 4;
        // A: 128 rows x 8 chunks of 16B
        #pragma unroll
        for (int u = 0; u < 4; u++) {
            int c = tid + u * 256;
            int r = c >> 3, j = c & 7;
            int xi = (r & 63) + kx - 1;
            int yi = y0 + (r >> 6) + ky - 1;
            bool ok = ((unsigned)xi < WW) && ((unsigned)yi < HH);
            const float* src = ok ? (Ab + ((size_t)(yi * WW + xi)) * CTOT + kc * 32 + j * 4)
                                  : Ab;
            cp_async16(st_base + (uint32_t)(r * (A_STRIDE * 4) + j * 16), src, ok ? 16u : 0u);
        }
        // B: 256 rows x 8 chunks of 16B
        const float* Wsrc = g_W + (size_t)it * NGATE * 32;
        const uint32_t b_base = st_base + A_STAGE_F * 4;
        #pragma unroll
        for (int u = 0; u < 8; u++) {
            int c = tid + u * 256;
            int r = c >> 3, j = c & 7;
            cp_async16(b_base + (uint32_t)(r * (A_STRIDE * 4) + j * 16),
                       Wsrc + r * 32 + j * 4, 16u);
        }
        CP_COMMIT();
    };

    prefetch(0, 0);
    prefetch(1, 1);
    for (int it = 0; it < NITER; it++) {
        const int s = it % NSTAGE;
        if (it + 1 < NITER) { CP_WAIT(1); } else { CP_WAIT(0); }
        __syncthreads();
        if (it + 2 < NITER) prefetch(it + 2, (it + 2) % NSTAGE);

        const float* As_ = smf + s * STAGE_F;
        const float* Bs_ = smf + s * STAGE_F + A_STAGE_F;

        #pragma unroll
        for (int ks = 0; ks < 4; ks++) {
            const int ko = ks * 8 + tig * 2;
            float2 afr[4][2];
            #pragma unroll
            for (int mi = 0; mi < 4; mi++) {
                afr[mi][0] = *(const float2*)(As_ + (warp_m + mi * 16 + gid) * A_STRIDE + ko);
                afr[mi][1] = *(const float2*)(As_ + (warp_m + mi * 16 + 8 + gid) * A_STRIDE + ko);
            }
            float2 bfr[8];
            #pragma unroll
            for (int ni = 0; ni < 8; ni++)
                bfr[ni] = *(const float2*)(Bs_ + (warp_n + ni * 8 + gid) * A_STRIDE + ko);

            #pragma unroll
            for (int mi = 0; mi < 4; mi++)
                #pragma unroll
                for (int ni = 0; ni < 8; ni++)
                    mma_tf32(acc[mi][ni],
                             __float_as_uint(afr[mi][0].x), __float_as_uint(afr[mi][1].x),
                             __float_as_uint(afr[mi][0].y), __float_as_uint(afr[mi][1].y),
                             __float_as_uint(bfr[ni].x),    __float_as_uint(bfr[ni].y));
        }
    }

    // ---- fused LSTM epilogue, registers + lane-pair shfl ----
    // col(n) = warp_n + ni*8 + tig*2 + {0,1}; n = hc*4 + gate
    const int odd = tig & 1;
    #pragma unroll
    for (int mi = 0; mi < 4; mi++) {
        #pragma unroll
        for (int ni = 0; ni < 8; ni++) {
            float c0 = acc[mi][ni][0], c1 = acc[mi][ni][1];
            float c2 = acc[mi][ni][2], c3 = acc[mi][ni][3];
            float e0 = __shfl_xor_sync(0xFFFFFFFFu, odd ? c0 : c2, 1);
            float e1 = __shfl_xor_sync(0xFFFFFFFFu, odd ? c1 : c3, 1);
            float zi, zf, zo, zg;
            int row;
            if (!odd) { zi = c0; zf = c1; zo = e0; zg = e1; row = warp_m + mi * 16 + gid; }
            else      { zi = e0; zf = e1; zo = c2; zg = c3; row = warp_m + mi * 16 + gid + 8; }
            const int hc = (warp_n >> 2) + ni * 2 + (tig >> 1);
            const float4 bv = *(const float4*)(g_bias + hc * 4);
            zi += bv.x; zf += bv.y; zo += bv.z; zg += bv.w;

            float ig = fsigmoid(zi), fg = fsigmoid(zf), og = fsigmoid(zo);
            float gg = ftanh(zg);
            const int y = y0 + (row >> 6);
            const int x = row & 63;
            size_t cidx = ((size_t)(b * HCC + hc) * HH + y) * WW + x;
            float cn = fg * cs[cidx] + ig * gg;
            hout[cidx] = og * ftanh(cn);
            cout[cidx] = cn;
        }
    }
}

// ---------------- host ----------------
extern "C" void kernel_launch(void* const* d_in, const int* in_sizes, int n_in,
                              void* d_out, int out_size) {
    const float* x  = (const float*)d_in[0];
    const float* hs = (const float*)d_in[1];
    const float* cs = (const float*)d_in[2];

    const float *WX[4], *BX[4], *WH[4], *BH[4];
    if (in_sizes[4] == HCC) {           // interleaved: w_xi,b_xi,w_xf,b_xf,...
        for (int g = 0; g < 4; g++) {
            WX[g] = (const float*)d_in[3 + 2 * g];
            BX[g] = (const float*)d_in[4 + 2 * g];
            WH[g] = (const float*)d_in[11 + 2 * g];
            BH[g] = (const float*)d_in[12 + 2 * g];
        }
    } else {                            // grouped
        for (int g = 0; g < 4; g++) {
            WX[g] = (const float*)d_in[3 + g];
            BX[g] = (const float*)d_in[7 + g];
            WH[g] = (const float*)d_in[11 + g];
            BH[g] = (const float*)d_in[15 + g];
        }
    }

    float* hout = (float*)d_out;
    float* cout = hout + (size_t)BB * HCC * HH * WW;

    pack_input<<<BB * HH, 256>>>(x, hs);
    pack_weights<<<(NITER * NGATE * 32 + 255) / 256, 256>>>(
        WX[0], WX[1], WX[2], WX[3], WH[0], WH[1], WH[2], WH[3],
        BX[0], BX[1], BX[2], BX[3], BH[0], BH[1], BH[2], BH[3]);

    cudaFuncSetAttribute(convlstm_mma, cudaFuncAttributeMaxDynamicSharedMemorySize, SMEM_BYTES);
    convlstm_mma<<<1024, 256, SMEM_BYTES>>>(cs, hout, cout);
}

// round 6
// speedup vs baseline: 5.1972x; 1.4305x over previous
#include <cuda_runtime.h>
#include <cuda_fp16.h>
#include <cstdint>

#define BB   32
#define CIN  32
#define HCC  64
#define HH   64
#define WW   64
#define CTOT 96          // 32 x-channels + 64 h-channels
#define NGATE 256        // 64 hc * 4 gates, packed n = hc*4 + gate
#define NITER 27         // 9 taps * 3 channel-chunks of 32

// ---------------- device scratch (static, allocation-free) ----------------
__device__ __half g_A[(size_t)BB * HH * WW * CTOT];  // [b][y][x][c'] k-perm, fp16
__device__ __half g_W[NITER * NGATE * 32];           // [tap*3+kc][hc*4+gate][ci'] perm
__device__ float  g_bias[NGATE];                     // [hc*4+gate]

// k-permutation within a 32-chunk: stored position p holds original local k:
//   k(p) = 2*(p>>3) + (p&1) + ((p>>1)&3)*8
__device__ __forceinline__ int kperm(int p) {
    return 2 * (p >> 3) + (p & 1) + (((p >> 1) & 3) << 3);
}

// ---------------- helpers ----------------
__device__ __forceinline__ void cp_async16(uint32_t dst, const void* src, uint32_t sz) {
    asm volatile("cp.async.cg.shared.global [%0], [%1], 16, %2;"
                 :: "r"(dst), "l"(src), "r"(sz) : "memory");
}
__device__ __forceinline__ uint32_t smem_u32(const void* p) {
    uint32_t a;
    asm("{ .reg .u64 t; cvta.to.shared.u64 t, %1; cvt.u32.u64 %0, t; }" : "=r"(a) : "l"(p));
    return a;
}
#define CP_COMMIT() asm volatile("cp.async.commit_group;" ::: "memory")
#define CP_WAIT(n)  asm volatile("cp.async.wait_group %0;" :: "n"(n) : "memory")

__device__ __forceinline__ void mma_f16(float* d, uint32_t a0, uint32_t a1, uint32_t a2,
                                        uint32_t a3, uint32_t b0, uint32_t b1) {
    asm volatile(
        "mma.sync.aligned.m16n8k16.row.col.f32.f16.f16.f32 "
        "{%0,%1,%2,%3}, {%4,%5,%6,%7}, {%8,%9}, {%0,%1,%2,%3};"
        : "+f"(d[0]), "+f"(d[1]), "+f"(d[2]), "+f"(d[3])
        : "r"(a0), "r"(a1), "r"(a2), "r"(a3), "r"(b0), "r"(b1));
}

__device__ __forceinline__ float fsigmoid(float v) {
    float e;
    asm("ex2.approx.f32 %0, %1;" : "=f"(e) : "f"(-v * 1.4426950408889634f));
    float r;
    asm("rcp.approx.f32 %0, %1;" : "=f"(r) : "f"(1.0f + e));
    return r;
}
__device__ __forceinline__ float ftanh(float v) {
    float e;
    asm("ex2.approx.f32 %0, %1;" : "=f"(e) : "f"(v * 2.885390081777927f));  // e^(2v)
    float r;
    asm("rcp.approx.f32 %0, %1;" : "=f"(r) : "f"(1.0f + e));
    return 1.0f - 2.0f * r;
}

// ---------------- pre-pass 1: NCHW x||h -> NHWC g_A (fp16, k-perm channels) --------
__global__ __launch_bounds__(256) void pack_input(const float* __restrict__ x,
                                                  const float* __restrict__ hs) {
    __shared__ float sm[CTOT * 65];
    int b = blockIdx.x >> 6;
    int y = blockIdx.x & 63;
    int t = threadIdx.x;
    for (int idx = t; idx < CTOT * 64; idx += 256) {
        int c = idx >> 6, xp = idx & 63;
        float v;
        if (c < CIN) v = x[((size_t)(b * CIN + c) * HH + y) * WW + xp];
        else         v = hs[((size_t)(b * HCC + (c - CIN)) * HH + y) * WW + xp];
        sm[c * 65 + xp] = v;
    }
    __syncthreads();
    __half* dst = g_A + (size_t)(b * HH + y) * WW * CTOT;
    for (int o = t; o < CTOT * 64; o += 256) {
        int xp = o / CTOT, cpos = o - xp * CTOT;
        int c = (cpos & ~31) + kperm(cpos & 31);
        dst[o] = __float2half_rn(sm[c * 65 + xp]);
    }
}

// ---------------- pre-pass 2: weights -> g_W [tap*3+kc][hc*4+gate][ci'] ------------
__global__ __launch_bounds__(256) void pack_weights(
    const float* wxi, const float* wxf, const float* wxo, const float* wxg,
    const float* whi, const float* whf, const float* who, const float* whg,
    const float* bxi, const float* bxf, const float* bxo, const float* bxg,
    const float* bhi, const float* bhf, const float* bho, const float* bhg) {
    const float* wx[4] = {wxi, wxf, wxo, wxg};
    const float* wh[4] = {whi, whf, who, whg};
    int g = blockIdx.x * 256 + threadIdx.x;
    if (g < NITER * NGATE * 32) {
        int ci = g & 31;                          // stored position
        int r = g >> 5;
        int n = r & 255;
        int tk = r >> 8;                          // tap*3 + kc
        int tap = tk / 3, kc = tk - 3 * tap;
        int ky = tap / 3, kx = tap - 3 * ky;
        int hc = n >> 2, gate = n & 3;
        int cg = kc * 32 + kperm(ci);             // original channel
        float v;
        if (cg < CIN) v = wx[gate][((hc * CIN + cg) * 3 + ky) * 3 + kx];
        else          v = wh[gate][((hc * HCC + (cg - CIN)) * 3 + ky) * 3 + kx];
        g_W[g] = __float2half_rn(v);
    }
    if (blockIdx.x == 0) {
        const float* bx[4] = {bxi, bxf, bxo, bxg};
        const float* bh[4] = {bhi, bhf, bho, bhg};
        int t = threadIdx.x;          // n = hc*4+gate
        int hc = t >> 2, gate = t & 3;
        g_bias[t] = bx[gate][hc] + bh[gate][hc];
    }
}

// ---------------- main mma.sync fp16 kernel ----------------
#define A_ROW_H  32                         // halves per row (64 B)
#define A_ROWS   128
#define B_ROWS   256
#define A_STAGE_H (A_ROWS * A_ROW_H)        // 4096 halves
#define STAGE_H  ((A_ROWS + B_ROWS) * A_ROW_H)   // 12288 halves = 24576 B
#define NSTAGE 3
#define SMEM_BYTES (NSTAGE * STAGE_H * 2)   // 73728

__global__ __launch_bounds__(256, 1) void convlstm_mma(
    const float* __restrict__ cs, float* __restrict__ hout, float* __restrict__ cout) {
    extern __shared__ __half smh[];
    const uint32_t sb = smem_u32(smh);
    const int tid  = threadIdx.x;
    const int wid  = tid >> 5;
    const int lane = tid & 31;
    const int gid  = lane >> 2;        // 0..7
    const int tig  = lane & 3;         // 0..3
    const int warp_m = (wid >> 2) * 64;   // 2 warps over M
    const int warp_n = (wid & 3) * 64;    // 4 warps over N

    const int b  = blockIdx.x >> 5;
    const int y0 = (blockIdx.x & 31) * 2;
    const __half* Ab = g_A + (size_t)b * HH * WW * CTOT;

    float acc[4][8][4];
    #pragma unroll
    for (int mi = 0; mi < 4; mi++)
        #pragma unroll
        for (int ni = 0; ni < 8; ni++)
            #pragma unroll
            for (int q = 0; q < 4; q++) acc[mi][ni][q] = 0.0f;

    // ---- async tile loader for iteration `it` into stage s (16B chunks) ----
    auto prefetch = [&](int it, int s) {
        const int tap = it / 3, kc = it - 3 * tap;
        const int ky = tap / 3, kx = tap - 3 * ky;
        const uint32_t st_base = sb + (uint32_t)(s * STAGE_H) * 2;
        // A: 128 rows x 4 chunks of 16B
        #pragma unroll
        for (int u = 0; u < 2; u++) {
            int c = tid + u * 256;
            int r = c >> 2, j = c & 3;
            int xi = (r & 63) + kx - 1;
            int yi = y0 + (r >> 6) + ky - 1;
            bool ok = ((unsigned)xi < WW) && ((unsigned)yi < HH);
            const __half* src = ok ? (Ab + ((size_t)(yi * WW + xi)) * CTOT + kc * 32 + j * 8)
                                   : Ab;
            cp_async16(st_base + (uint32_t)(r * 64 + j * 16), src, ok ? 16u : 0u);
        }
        // B: 256 rows x 4 chunks of 16B
        const __half* Wsrc = g_W + (size_t)it * NGATE * 32;
        const uint32_t b_base = st_base + A_STAGE_H * 2;
        #pragma unroll
        for (int u = 0; u < 4; u++) {
            int c = tid + u * 256;
            int r = c >> 2, j = c & 3;
            cp_async16(b_base + (uint32_t)(r * 64 + j * 16), Wsrc + r * 32 + j * 8, 16u);
        }
        CP_COMMIT();
    };

    prefetch(0, 0);
    prefetch(1, 1);
    for (int it = 0; it < NITER; it++) {
        const int s = it % NSTAGE;
        if (it + 1 < NITER) { CP_WAIT(1); } else { CP_WAIT(0); }
        __syncthreads();
        if (it + 2 < NITER) prefetch(it + 2, (it + 2) % NSTAGE);

        const __half* As_ = smh + s * STAGE_H;
        const __half* Bs_ = smh + s * STAGE_H + A_STAGE_H;

        // one LDS.128 per row fetches this thread's fragment for BOTH k-halves
        uint4 afr[8];   // [mi*2 + (row>=+8)]
        #pragma unroll
        for (int mi = 0; mi < 4; mi++) {
            afr[mi * 2 + 0] = *(const uint4*)(As_ + (warp_m + mi * 16 + gid) * A_ROW_H + tig * 8);
            afr[mi * 2 + 1] = *(const uint4*)(As_ + (warp_m + mi * 16 + 8 + gid) * A_ROW_H + tig * 8);
        }
        uint4 bfr[8];
        #pragma unroll
        for (int ni = 0; ni < 8; ni++)
            bfr[ni] = *(const uint4*)(Bs_ + (warp_n + ni * 8 + gid) * A_ROW_H + tig * 8);

        #pragma unroll
        for (int mi = 0; mi < 4; mi++)
            #pragma unroll
            for (int ni = 0; ni < 8; ni++)
                mma_f16(acc[mi][ni],
                        afr[mi * 2].x, afr[mi * 2 + 1].x, afr[mi * 2].y, afr[mi * 2 + 1].y,
                        bfr[ni].x, bfr[ni].y);
        #pragma unroll
        for (int mi = 0; mi < 4; mi++)
            #pragma unroll
            for (int ni = 0; ni < 8; ni++)
                mma_f16(acc[mi][ni],
                        afr[mi * 2].z, afr[mi * 2 + 1].z, afr[mi * 2].w, afr[mi * 2 + 1].w,
                        bfr[ni].z, bfr[ni].w);
    }

    // ---- fused LSTM epilogue, registers + lane-pair shfl ----
    // col(n) = warp_n + ni*8 + tig*2 + {0,1}; n = hc*4 + gate
    const int odd = tig & 1;
    #pragma unroll
    for (int mi = 0; mi < 4; mi++) {
        #pragma unroll
        for (int ni = 0; ni < 8; ni++) {
            float c0 = acc[mi][ni][0], c1 = acc[mi][ni][1];
            float c2 = acc[mi][ni][2], c3 = acc[mi][ni][3];
            float e0 = __shfl_xor_sync(0xFFFFFFFFu, odd ? c0 : c2, 1);
            float e1 = __shfl_xor_sync(0xFFFFFFFFu, odd ? c1 : c3, 1);
            float zi, zf, zo, zg;
            int row;
            if (!odd) { zi = c0; zf = c1; zo = e0; zg = e1; row = warp_m + mi * 16 + gid; }
            else      { zi = e0; zf = e1; zo = c2; zg = c3; row = warp_m + mi * 16 + gid + 8; }
            const int hc = (warp_n >> 2) + ni * 2 + (tig >> 1);
            const float4 bv = *(const float4*)(g_bias + hc * 4);
            zi += bv.x; zf += bv.y; zo += bv.z; zg += bv.w;

            float ig = fsigmoid(zi), fg = fsigmoid(zf), og = fsigmoid(zo);
            float gg = ftanh(zg);
            const int y = y0 + (row >> 6);
            const int x = row & 63;
            size_t cidx = ((size_t)(b * HCC + hc) * HH + y) * WW + x;
            float cn = fg * cs[cidx] + ig * gg;
            hout[cidx] = og * ftanh(cn);
            cout[cidx] = cn;
        }
    }
}

// ---------------- host ----------------
extern "C" void kernel_launch(void* const* d_in, const int* in_sizes, int n_in,
                              void* d_out, int out_size) {
    const float* x  = (const float*)d_in[0];
    const float* hs = (const float*)d_in[1];
    const float* cs = (const float*)d_in[2];

    const float *WX[4], *BX[4], *WH[4], *BH[4];
    if (in_sizes[4] == HCC) {           // interleaved: w_xi,b_xi,w_xf,b_xf,...
        for (int g = 0; g < 4; g++) {
            WX[g] = (const float*)d_in[3 + 2 * g];
            BX[g] = (const float*)d_in[4 + 2 * g];
            WH[g] = (const float*)d_in[11 + 2 * g];
            BH[g] = (const float*)d_in[12 + 2 * g];
        }
    } else {                            // grouped
        for (int g = 0; g < 4; g++) {
            WX[g] = (const float*)d_in[3 + g];
            BX[g] = (const float*)d_in[7 + g];
            WH[g] = (const float*)d_in[11 + g];
            BH[g] = (const float*)d_in[15 + g];
        }
    }

    float* hout = (float*)d_out;
    float* cout = hout + (size_t)BB * HCC * HH * WW;

    pack_input<<<BB * HH, 256>>>(x, hs);
    pack_weights<<<(NITER * NGATE * 32 + 255) / 256, 256>>>(
        WX[0], WX[1], WX[2], WX[3], WH[0], WH[1], WH[2], WH[3],
        BX[0], BX[1], BX[2], BX[3], BH[0], BH[1], BH[2], BH[3]);

    cudaFuncSetAttribute(convlstm_mma, cudaFuncAttributeMaxDynamicSharedMemorySize, SMEM_BYTES);
    convlstm_mma<<<1024, 256, SMEM_BYTES>>>(cs, hout, cout);
}

// round 7
// speedup vs baseline: 6.1262x; 1.1787x over previous
#include <cuda_runtime.h>
#include <cuda_fp16.h>
#include <cstdint>

#define BB   32
#define CIN  32
#define HCC  64
#define HH   64
#define WW   64
#define CTOT 96
#define NGATE 256        // n = hc*4 + gate
#define NITER 27

// ---------------- device scratch ----------------
__device__ __half g_A[(size_t)BB * HH * WW * CTOT];  // [b][y][x][c'] k-perm fp16
__device__ __half g_W[NITER * NGATE * 32];           // [tap*3+kc][hc*4+gate][ci']
__device__ float  g_bias[NGATE];

__device__ __forceinline__ int kperm(int p) {        // stored pos -> original k
    return 2 * (p >> 3) + (p & 1) + (((p >> 1) & 3) << 3);
}
__device__ __forceinline__ void cp_async16(uint32_t dst, const void* src, uint32_t sz) {
    asm volatile("cp.async.cg.shared.global [%0], [%1], 16, %2;"
                 :: "r"(dst), "l"(src), "r"(sz) : "memory");
}
__device__ __forceinline__ uint32_t smem_u32(const void* p) {
    uint32_t a;
    asm("{ .reg .u64 t; cvta.to.shared.u64 t, %1; cvt.u32.u64 %0, t; }" : "=r"(a) : "l"(p));
    return a;
}
#define CP_COMMIT() asm volatile("cp.async.commit_group;" ::: "memory")
#define CP_WAIT(n)  asm volatile("cp.async.wait_group %0;" :: "n"(n) : "memory")

__device__ __forceinline__ void mma_f16(float* d, uint32_t a0, uint32_t a1, uint32_t a2,
                                        uint32_t a3, uint32_t b0, uint32_t b1) {
    asm volatile(
        "mma.sync.aligned.m16n8k16.row.col.f32.f16.f16.f32 "
        "{%0,%1,%2,%3}, {%4,%5,%6,%7}, {%8,%9}, {%0,%1,%2,%3};"
        : "+f"(d[0]), "+f"(d[1]), "+f"(d[2]), "+f"(d[3])
        : "r"(a0), "r"(a1), "r"(a2), "r"(a3), "r"(b0), "r"(b1));
}
__device__ __forceinline__ float fsigmoid(float v) {
    float e; asm("ex2.approx.f32 %0, %1;" : "=f"(e) : "f"(-v * 1.4426950408889634f));
    float r; asm("rcp.approx.f32 %0, %1;" : "=f"(r) : "f"(1.0f + e));
    return r;
}
__device__ __forceinline__ float ftanh(float v) {
    float e; asm("ex2.approx.f32 %0, %1;" : "=f"(e) : "f"(v * 2.885390081777927f));
    float r; asm("rcp.approx.f32 %0, %1;" : "=f"(r) : "f"(1.0f + e));
    return 1.0f - 2.0f * r;
}

// ---------------- merged pre-pass ----------------
__global__ __launch_bounds__(256) void pack_all(
    const float* __restrict__ x, const float* __restrict__ hs,
    const float* wxi, const float* wxf, const float* wxo, const float* wxg,
    const float* whi, const float* whf, const float* who, const float* whg,
    const float* bxi, const float* bxf, const float* bxo, const float* bxg,
    const float* bhi, const float* bhf, const float* bho, const float* bhg) {
    const int blk = blockIdx.x;
    const int t = threadIdx.x;
    if (blk < 2048) {
        __shared__ float sm[CTOT * 65];
        int b = blk >> 6, y = blk & 63;
        #pragma unroll
        for (int i = 0; i < 6; i++) {
            int u = t + i * 256;
            int c = u >> 4, x4 = (u & 15) * 4;
            const float* src = (c < CIN)
                ? x  + ((size_t)(b * CIN + c) * HH + y) * WW + x4
                : hs + ((size_t)(b * HCC + (c - CIN)) * HH + y) * WW + x4;
            float4 v = *(const float4*)src;
            float* d = sm + c * 65 + x4;
            d[0] = v.x; d[1] = v.y; d[2] = v.z; d[3] = v.w;
        }
        __syncthreads();
        __half* dst = g_A + (size_t)(b * HH + y) * WW * CTOT;
        int o = t, xp = t / 96, cpos = t - xp * 96;
        #pragma unroll
        for (int k = 0; k < 24; k++) {
            int c = (cpos & ~31) + kperm(cpos & 31);
            dst[o] = __float2half_rn(sm[c * 65 + xp]);
            o += 256; cpos += 64; xp += 2;
            if (cpos >= 96) { cpos -= 96; xp += 1; }
        }
    } else if (blk < 2912) {
        const float* wx[4] = {wxi, wxf, wxo, wxg};
        const float* wh[4] = {whi, whf, who, whg};
        int g = (blk - 2048) * 256 + t;
        int ci = g & 31;
        int r = g >> 5;
        int n = r & 255;
        int tk = r >> 8;
        int tap = tk / 3, kc = tk - 3 * tap;
        int ky = tap / 3, kx = tap - 3 * ky;
        int hc = n >> 2, gate = n & 3;
        int cg = kc * 32 + kperm(ci);
        float v;
        if (cg < CIN) v = wx[gate][((hc * CIN + cg) * 3 + ky) * 3 + kx];
        else          v = wh[gate][((hc * HCC + (cg - CIN)) * 3 + ky) * 3 + kx];
        g_W[g] = __float2half_rn(v);
    } else {
        const float* bx[4] = {bxi, bxf, bxo, bxg};
        const float* bh[4] = {bhi, bhf, bho, bhg};
        int hc = t >> 2, gate = t & 3;
        g_bias[t] = bx[gate][hc] + bh[gate][hc];
    }
}

// ---------------- main kernel ----------------
#define AREG_B   16896
#define AREG_H   8448
#define A_TOTAL  (3 * AREG_B)                  // 50688 bytes
#define B_STAGE_B 16384
#define SMEM_BYTES (A_TOTAL + 3 * B_STAGE_B)   // 99840

__global__ __launch_bounds__(256, 1) void convlstm_mma(
    const float* __restrict__ cs, float* __restrict__ hout, float* __restrict__ cout) {
    extern __shared__ __half smh[];
    const uint32_t sb = smem_u32(smh);
    const int tid  = threadIdx.x;
    const int lane = tid & 31;
    const int wid  = tid >> 5;
    const int gid  = lane >> 2;
    const int tig  = lane & 3;
    const int warp_m = (wid >> 2) * 64;
    const int warpY  = warp_m >> 6;
    const int warp_n = (wid & 3) * 64;

    const int b  = blockIdx.x >> 5;
    const int y0 = (blockIdx.x & 31) * 2;
    const __half* Ab = g_A + (size_t)b * HH * WW * CTOT;

    float acc[4][8][4];
    #pragma unroll
    for (int mi = 0; mi < 4; mi++)
        #pragma unroll
        for (int ni = 0; ni < 8; ni++)
            #pragma unroll
            for (int q = 0; q < 4; q++) acc[mi][ni][q] = 0.0f;

    auto prefetchB = [&](int it, int s) {
        const __half* Wsrc = g_W + (size_t)it * (NGATE * 32);
        const uint32_t bb = sb + A_TOTAL + (uint32_t)s * B_STAGE_B;
        #pragma unroll
        for (int u = 0; u < 4; u++) {
            int c = tid + u * 256;
            int r = c >> 2, j = c & 3;
            cp_async16(bb + (uint32_t)(r * 64 + j * 16), Wsrc + r * 32 + j * 8, 16u);
        }
        CP_COMMIT();
    };

    // A-resident fill: 3 kc regions x 4 rows x 66 cols x 64B
    for (int i = tid; i < 3168; i += 256) {
        int j = i & 3;
        int rest = i >> 2;
        int xx = rest % 66;
        int r2 = rest / 66;
        int yy = r2 & 3, kc = r2 >> 2;
        int gy = y0 + yy - 1, gx = xx - 1;
        bool ok = ((unsigned)gy < HH) && ((unsigned)gx < WW);
        const __half* src = ok ? (Ab + ((size_t)(gy * WW + gx)) * CTOT + kc * 32 + j * 8)
                               : Ab;
        cp_async16(sb + (uint32_t)(kc * AREG_B + (yy * 66 + xx) * 64 + j * 16),
                   src, ok ? 16u : 0u);
    }
    CP_COMMIT();
    prefetchB(0, 0);
    prefetchB(1, 1);

    int kc = 0, ky = 0, kx = 0;
    for (int it = 0; it < NITER; it++) {
        if (it + 1 < NITER) { CP_WAIT(1); } else { CP_WAIT(0); }
        __syncthreads();
        if (it + 2 < NITER) {
            int it2 = it + 2;
            prefetchB(it2, it2 % 3);
        }
        const int s = it % 3;

        const __half* As_ = smh + kc * AREG_H + ((warpY + ky) * 66 + kx) * 32;
        uint4 afr[8];
        #pragma unroll
        for (int mi = 0; mi < 4; mi++) {
            afr[mi * 2 + 0] = *(const uint4*)(As_ + (mi * 16 + gid) * 32 + tig * 8);
            afr[mi * 2 + 1] = *(const uint4*)(As_ + (mi * 16 + 8 + gid) * 32 + tig * 8);
        }
        const __half* Bs_ = smh + (A_TOTAL / 2) + s * (B_STAGE_B / 2);
        uint4 bfr[8];
        #pragma unroll
        for (int ni = 0; ni < 8; ni++)
            bfr[ni] = *(const uint4*)(Bs_ + (warp_n + ni * 8 + gid) * 32 + tig * 8);

        #pragma unroll
        for (int mi = 0; mi < 4; mi++)
            #pragma unroll
            for (int ni = 0; ni < 8; ni++)
                mma_f16(acc[mi][ni],
                        afr[mi * 2].x, afr[mi * 2 + 1].x, afr[mi * 2].y, afr[mi * 2 + 1].y,
                        bfr[ni].x, bfr[ni].y);
        #pragma unroll
        for (int mi = 0; mi < 4; mi++)
            #pragma unroll
            for (int ni = 0; ni < 8; ni++)
                mma_f16(acc[mi][ni],
                        afr[mi * 2].z, afr[mi * 2 + 1].z, afr[mi * 2].w, afr[mi * 2 + 1].w,
                        bfr[ni].z, bfr[ni].w);

        if (++kc == 3) { kc = 0; if (++kx == 3) { kx = 0; ky++; } }
    }

    const int odd = tig & 1;
    #pragma unroll
    for (int mi = 0; mi < 4; mi++) {
        #pragma unroll
        for (int ni = 0; ni < 8; ni++) {
            float c0 = acc[mi][ni][0], c1 = acc[mi][ni][1];
            float c2 = acc[mi][ni][2], c3 = acc[mi][ni][3];
            float e0 = __shfl_xor_sync(0xFFFFFFFFu, odd ? c0 : c2, 1);
            float e1 = __shfl_xor_sync(0xFFFFFFFFu, odd ? c1 : c3, 1);
            float zi, zf, zo, zg;
            int row;
            if (!odd) { zi = c0; zf = c1; zo = e0; zg = e1; row = warp_m + mi * 16 + gid; }
            else      { zi = e0; zf = e1; zo = c2; zg = c3; row = warp_m + mi * 16 + gid + 8; }
            const int hc = (warp_n >> 2) + ni * 2 + (tig >> 1);
            const float4 bv = *(const float4*)(g_bias + hc * 4);
            zi += bv.x; zf += bv.y; zo += bv.z; zg += bv.w;
            float ig = fsigmoid(zi), fg = fsigmoid(zf), og = fsigmoid(zo);
            float gg = ftanh(zg);
            const int y = y0 + (row >> 6);
            const int x = row & 63;
            size_t cidx = ((size_t)(b * HCC + hc) * HH + y) * WW + x;
            float cn = fg * cs[cidx] + ig * gg;
            hout[cidx] = og * ftanh(cn);
            cout[cidx] = cn;
        }
    }
}

// ---------------- host ----------------
extern "C" void kernel_launch(void* const* d_in, const int* in_sizes, int n_in,
                              void* d_out, int out_size) {
    const float* x  = (const float*)d_in[0];
    const float* hs = (const float*)d_in[1];
    const float* cs = (const float*)d_in[2];

    const float *WX[4], *BX[4], *WH[4], *BH[4];
    if (in_sizes[4] == HCC) {
        for (int g = 0; g < 4; g++) {
            WX[g] = (const float*)d_in[3 + 2 * g];
            BX[g] = (const float*)d_in[4 + 2 * g];
            WH[g] = (const float*)d_in[11 + 2 * g];
            BH[g] = (const float*)d_in[12 + 2 * g];
        }
    } else {
        for (int g = 0; g < 4; g++) {
            WX[g] = (const float*)d_in[3 + g];
            BX[g] = (const float*)d_in[7 + g];
            WH[g] = (const float*)d_in[11 + g];
            BH[g] = (const float*)d_in[15 + g];
        }
    }

    float* hout = (float*)d_out;
    float* cout = hout + (size_t)BB * HCC * HH * WW;

    pack_all<<<2913, 256>>>(x, hs,
        WX[0], WX[1], WX[2], WX[3], WH[0], WH[1], WH[2], WH[3],
        BX[0], BX[1], BX[2], BX[3], BH[0], BH[1], BH[2], BH[3]);

    cudaFuncSetAttribute(convlstm_mma, cudaFuncAttributeMaxDynamicSharedMemorySize, SMEM_BYTES);
    convlstm_mma<<<1024, 256, SMEM_BYTES>>>(cs, hout, cout);
}

// round 8
// speedup vs baseline: 6.9860x; 1.1404x over previous
#include <cuda_runtime.h>
#include <cuda_fp16.h>
#include <cstdint>

#define BB   32
#define CIN  32
#define HCC  64
#define HH   64
#define WW   64
#define CTOT 96
#define NGATE 256        // n = hc*4 + gate
#define NITER 27

// ---------------- device scratch ----------------
__device__ __half g_A[(size_t)BB * HH * WW * CTOT];  // [b][y][x][c'] k-perm fp16
__device__ __half g_W[NITER * NGATE * 32];           // [tap*3+kc][hc*4+gate][ci']
__device__ float  g_bias[NGATE];

__device__ __forceinline__ int kperm(int p) {        // stored pos -> original k
    return 2 * (p >> 3) + (p & 1) + (((p >> 1) & 3) << 3);
}
__device__ __forceinline__ void cp_async16(uint32_t dst, const void* src, uint32_t sz) {
    asm volatile("cp.async.cg.shared.global [%0], [%1], 16, %2;"
                 :: "r"(dst), "l"(src), "r"(sz) : "memory");
}
__device__ __forceinline__ uint32_t smem_u32(const void* p) {
    uint32_t a;
    asm("{ .reg .u64 t; cvta.to.shared.u64 t, %1; cvt.u32.u64 %0, t; }" : "=r"(a) : "l"(p));
    return a;
}
#define CP_COMMIT() asm volatile("cp.async.commit_group;" ::: "memory")
#define CP_WAIT(n)  asm volatile("cp.async.wait_group %0;" :: "n"(n) : "memory")

__device__ __forceinline__ void mma_f16(float* d, uint32_t a0, uint32_t a1, uint32_t a2,
                                        uint32_t a3, uint32_t b0, uint32_t b1) {
    asm volatile(
        "mma.sync.aligned.m16n8k16.row.col.f32.f16.f16.f32 "
        "{%0,%1,%2,%3}, {%4,%5,%6,%7}, {%8,%9}, {%0,%1,%2,%3};"
        : "+f"(d[0]), "+f"(d[1]), "+f"(d[2]), "+f"(d[3])
        : "r"(a0), "r"(a1), "r"(a2), "r"(a3), "r"(b0), "r"(b1));
}
__device__ __forceinline__ float fsigmoid(float v) {
    float e; asm("ex2.approx.f32 %0, %1;" : "=f"(e) : "f"(-v * 1.4426950408889634f));
    float r; asm("rcp.approx.f32 %0, %1;" : "=f"(r) : "f"(1.0f + e));
    return r;
}
__device__ __forceinline__ float ftanh(float v) {
    float e; asm("ex2.approx.f32 %0, %1;" : "=f"(e) : "f"(v * 2.885390081777927f));
    float r; asm("rcp.approx.f32 %0, %1;" : "=f"(r) : "f"(1.0f + e));
    return 1.0f - 2.0f * r;
}

// ---------------- merged pre-pass ----------------
__global__ __launch_bounds__(256) void pack_all(
    const float* __restrict__ x, const float* __restrict__ hs,
    const float* wxi, const float* wxf, const float* wxo, const float* wxg,
    const float* whi, const float* whf, const float* who, const float* whg,
    const float* bxi, const float* bxf, const float* bxo, const float* bxg,
    const float* bhi, const float* bhf, const float* bho, const float* bhg) {
    const int blk = blockIdx.x;
    const int t = threadIdx.x;
    if (blk < 2048) {
        __shared__ float sm[CTOT * 65];
        int b = blk >> 6, y = blk & 63;
        #pragma unroll
        for (int i = 0; i < 6; i++) {
            int u = t + i * 256;
            int c = u >> 4, x4 = (u & 15) * 4;
            const float* src = (c < CIN)
                ? x  + ((size_t)(b * CIN + c) * HH + y) * WW + x4
                : hs + ((size_t)(b * HCC + (c - CIN)) * HH + y) * WW + x4;
            float4 v = *(const float4*)src;
            float* d = sm + c * 65 + x4;
            d[0] = v.x; d[1] = v.y; d[2] = v.z; d[3] = v.w;
        }
        __syncthreads();
        __half* dst = g_A + (size_t)(b * HH + y) * WW * CTOT;
        int o = t, xp = t / 96, cpos = t - xp * 96;
        #pragma unroll
        for (int k = 0; k < 24; k++) {
            int c = (cpos & ~31) + kperm(cpos & 31);
            dst[o] = __float2half_rn(sm[c * 65 + xp]);
            o += 256; cpos += 64; xp += 2;
            if (cpos >= 96) { cpos -= 96; xp += 1; }
        }
    } else if (blk < 2912) {
        const float* wx[4] = {wxi, wxf, wxo, wxg};
        const float* wh[4] = {whi, whf, who, whg};
        int g = (blk - 2048) * 256 + t;
        int ci = g & 31;
        int r = g >> 5;
        int n = r & 255;
        int tk = r >> 8;
        int tap = tk / 3, kc = tk - 3 * tap;
        int ky = tap / 3, kx = tap - 3 * ky;
        int hc = n >> 2, gate = n & 3;
        int cg = kc * 32 + kperm(ci);
        float v;
        if (cg < CIN) v = wx[gate][((hc * CIN + cg) * 3 + ky) * 3 + kx];
        else          v = wh[gate][((hc * HCC + (cg - CIN)) * 3 + ky) * 3 + kx];
        g_W[g] = __float2half_rn(v);
    } else {
        const float* bx[4] = {bxi, bxf, bxo, bxg};
        const float* bh[4] = {bhi, bhf, bho, bhg};
        int hc = t >> 2, gate = t & 3;
        g_bias[t] = bx[gate][hc] + bh[gate][hc];
    }
}

// ---------------- main kernel ----------------
#define AREG_B   16896                          // bytes per kc region (4*66*64)
#define AREG_H   8448
#define A_TOTAL  (3 * AREG_B)                   // 50688 bytes
#define B_STAGE_B 8192                          // 128 rows * 64 B
#define SMEM_BYTES (A_TOTAL + 3 * B_STAGE_B)    // 75264 -> 2 CTAs/SM fits 228KB

__global__ __launch_bounds__(256, 2) void convlstm_mma(
    const float* __restrict__ cs, float* __restrict__ hout, float* __restrict__ cout) {
    extern __shared__ __half smh[];
    const uint32_t sb = smem_u32(smh);
    const int tid  = threadIdx.x;
    const int lane = tid & 31;
    const int wid  = tid >> 5;
    const int gid  = lane >> 2;
    const int tig  = lane & 3;
    const int warp_m = (wid >> 2) * 64;        // 2 warps over M (128)
    const int warpY  = warp_m >> 6;
    const int warp_n = (wid & 3) * 32;         // 4 warps over N (128)

    const int bx = blockIdx.x;
    const int nb = bx & 1;                     // N-half: hc [nb*32, nb*32+32)
    const int b  = bx >> 6;
    const int y0 = ((bx >> 1) & 31) * 2;
    const __half* Ab = g_A + (size_t)b * HH * WW * CTOT;

    float acc[4][4][4];
    #pragma unroll
    for (int mi = 0; mi < 4; mi++)
        #pragma unroll
        for (int ni = 0; ni < 4; ni++)
            #pragma unroll
            for (int q = 0; q < 4; q++) acc[mi][ni][q] = 0.0f;

    auto prefetchB = [&](int it, int s) {
        const __half* Wsrc = g_W + (size_t)it * (NGATE * 32) + nb * (128 * 32);
        const uint32_t bb = sb + A_TOTAL + (uint32_t)s * B_STAGE_B;
        #pragma unroll
        for (int u = 0; u < 2; u++) {
            int c = tid + u * 256;             // 0..511
            int r = c >> 2, j = c & 3;         // r 0..127
            cp_async16(bb + (uint32_t)(r * 64 + j * 16), Wsrc + r * 32 + j * 8, 16u);
        }
        CP_COMMIT();
    };

    // A-resident fill: 3 kc regions x 4 rows x 66 cols x 64B (3168 x 16B chunks)
    for (int i = tid; i < 3168; i += 256) {
        int j = i & 3;
        int rest = i >> 2;
        int xx = rest % 66;
        int r2 = rest / 66;
        int yy = r2 & 3, kc = r2 >> 2;
        int gy = y0 + yy - 1, gx = xx - 1;
        bool ok = ((unsigned)gy < HH) && ((unsigned)gx < WW);
        const __half* src = ok ? (Ab + ((size_t)(gy * WW + gx)) * CTOT + kc * 32 + j * 8)
                               : Ab;
        cp_async16(sb + (uint32_t)(kc * AREG_B + (yy * 66 + xx) * 64 + j * 16),
                   src, ok ? 16u : 0u);
    }
    CP_COMMIT();
    prefetchB(0, 0);
    prefetchB(1, 1);

    int kc = 0, ky = 0, kx = 0;
    for (int it = 0; it < NITER; it++) {
        if (it + 1 < NITER) { CP_WAIT(1); } else { CP_WAIT(0); }
        __syncthreads();
        if (it + 2 < NITER) prefetchB(it + 2, (it + 2) % 3);
        const int s = it % 3;

        const __half* As_ = smh + kc * AREG_H + ((warpY + ky) * 66 + kx) * 32 + tig * 8;
        const __half* Bs_ = smh + (A_TOTAL / 2) + s * (B_STAGE_B / 2)
                          + (warp_n + gid) * 32 + tig * 8;

        // k-half 0: uint2 fragments (keeps register footprint low)
        #pragma unroll
        for (int kh = 0; kh < 2; kh++) {
            const int ko = kh * 4;
            uint2 afr[8];
            #pragma unroll
            for (int mi = 0; mi < 4; mi++) {
                afr[mi * 2 + 0] = *(const uint2*)(As_ + (mi * 16 + gid) * 32 + ko);
                afr[mi * 2 + 1] = *(const uint2*)(As_ + (mi * 16 + 8 + gid) * 32 + ko);
            }
            uint2 bfr[4];
            #pragma unroll
            for (int ni = 0; ni < 4; ni++)
                bfr[ni] = *(const uint2*)(Bs_ + ni * 8 * 32 + ko);
            #pragma unroll
            for (int mi = 0; mi < 4; mi++)
                #pragma unroll
                for (int ni = 0; ni < 4; ni++)
                    mma_f16(acc[mi][ni],
                            afr[mi * 2].x, afr[mi * 2 + 1].x,
                            afr[mi * 2].y, afr[mi * 2 + 1].y,
                            bfr[ni].x, bfr[ni].y);
        }

        if (++kc == 3) { kc = 0; if (++kx == 3) { kx = 0; ky++; } }
    }

    // ---- fused LSTM epilogue ----
    const int odd = tig & 1;
    #pragma unroll
    for (int mi = 0; mi < 4; mi++) {
        #pragma unroll
        for (int ni = 0; ni < 4; ni++) {
            float c0 = acc[mi][ni][0], c1 = acc[mi][ni][1];
            float c2 = acc[mi][ni][2], c3 = acc[mi][ni][3];
            float e0 = __shfl_xor_sync(0xFFFFFFFFu, odd ? c0 : c2, 1);
            float e1 = __shfl_xor_sync(0xFFFFFFFFu, odd ? c1 : c3, 1);
            float zi, zf, zo, zg;
            int row;
            if (!odd) { zi = c0; zf = c1; zo = e0; zg = e1; row = warp_m + mi * 16 + gid; }
            else      { zi = e0; zf = e1; zo = c2; zg = c3; row = warp_m + mi * 16 + gid + 8; }
            const int hc = nb * 32 + (warp_n >> 2) + ni * 2 + (tig >> 1);
            const float4 bv = *(const float4*)(g_bias + hc * 4);
            zi += bv.x; zf += bv.y; zo += bv.z; zg += bv.w;
            float ig = fsigmoid(zi), fg = fsigmoid(zf), og = fsigmoid(zo);
            float gg = ftanh(zg);
            const int y = y0 + (row >> 6);
            const int x = row & 63;
            size_t cidx = ((size_t)(b * HCC + hc) * HH + y) * WW + x;
            float cn = fg * cs[cidx] + ig * gg;
            hout[cidx] = og * ftanh(cn);
            cout[cidx] = cn;
        }
    }
}

// ---------------- host ----------------
extern "C" void kernel_launch(void* const* d_in, const int* in_sizes, int n_in,
                              void* d_out, int out_size) {
    const float* x  = (const float*)d_in[0];
    const float* hs = (const float*)d_in[1];
    const float* cs = (const float*)d_in[2];

    const float *WX[4], *BX[4], *WH[4], *BH[4];
    if (in_sizes[4] == HCC) {
        for (int g = 0; g < 4; g++) {
            WX[g] = (const float*)d_in[3 + 2 * g];
            BX[g] = (const float*)d_in[4 + 2 * g];
            WH[g] = (const float*)d_in[11 + 2 * g];
            BH[g] = (const float*)d_in[12 + 2 * g];
        }
    } else {
        for (int g = 0; g < 4; g++) {
            WX[g] = (const float*)d_in[3 + g];
            BX[g] = (const float*)d_in[7 + g];
            WH[g] = (const float*)d_in[11 + g];
            BH[g] = (const float*)d_in[15 + g];
        }
    }

    float* hout = (float*)d_out;
    float* cout = hout + (size_t)BB * HCC * HH * WW;

    pack_all<<<2913, 256>>>(x, hs,
        WX[0], WX[1], WX[2], WX[3], WH[0], WH[1], WH[2], WH[3],
        BX[0], BX[1], BX[2], BX[3], BH[0], BH[1], BH[2], BH[3]);

    cudaFuncSetAttribute(convlstm_mma, cudaFuncAttributeMaxDynamicSharedMemorySize, SMEM_BYTES);
    convlstm_mma<<<2048, 256, SMEM_BYTES>>>(cs, hout, cout);
}

// round 9
// speedup vs baseline: 7.6092x; 1.0892x over previous
#include <cuda_runtime.h>
#include <cuda_fp16.h>
#include <cstdint>

#define BB   32
#define CIN  32
#define HCC  64
#define HH   64
#define WW   64
#define CTOT 96
#define NGATE 256        // n = hc*4 + gate
#define NITER 27

// ---------------- device scratch ----------------
__device__ __half g_A[(size_t)BB * HH * WW * CTOT];  // [b][y][x][c] natural order fp16
__device__ __half g_W[NITER * NGATE * 32];           // [tap*3+kc][hc*4+gate][ci]
__device__ float  g_bias[NGATE];

__device__ __forceinline__ void cp_async16(uint32_t dst, const void* src, uint32_t sz) {
    asm volatile("cp.async.cg.shared.global [%0], [%1], 16, %2;"
                 :: "r"(dst), "l"(src), "r"(sz) : "memory");
}
__device__ __forceinline__ uint32_t smem_u32(const void* p) {
    uint32_t a;
    asm("{ .reg .u64 t; cvta.to.shared.u64 t, %1; cvt.u32.u64 %0, t; }" : "=r"(a) : "l"(p));
    return a;
}
#define CP_COMMIT() asm volatile("cp.async.commit_group;" ::: "memory")
#define CP_WAIT(n)  asm volatile("cp.async.wait_group %0;" :: "n"(n) : "memory")

__device__ __forceinline__ void ldm4(uint32_t* r, uint32_t addr) {
    asm volatile("ldmatrix.sync.aligned.m8n8.x4.shared.b16 {%0,%1,%2,%3}, [%4];"
                 : "=r"(r[0]), "=r"(r[1]), "=r"(r[2]), "=r"(r[3]) : "r"(addr));
}
__device__ __forceinline__ void mma_f16(float* d, uint32_t a0, uint32_t a1, uint32_t a2,
                                        uint32_t a3, uint32_t b0, uint32_t b1) {
    asm volatile(
        "mma.sync.aligned.m16n8k16.row.col.f32.f16.f16.f32 "
        "{%0,%1,%2,%3}, {%4,%5,%6,%7}, {%8,%9}, {%0,%1,%2,%3};"
        : "+f"(d[0]), "+f"(d[1]), "+f"(d[2]), "+f"(d[3])
        : "r"(a0), "r"(a1), "r"(a2), "r"(a3), "r"(b0), "r"(b1));
}
__device__ __forceinline__ float fsigmoid(float v) {
    float e; asm("ex2.approx.f32 %0, %1;" : "=f"(e) : "f"(-v * 1.4426950408889634f));
    float r; asm("rcp.approx.f32 %0, %1;" : "=f"(r) : "f"(1.0f + e));
    return r;
}
__device__ __forceinline__ float ftanh(float v) {
    float e; asm("ex2.approx.f32 %0, %1;" : "=f"(e) : "f"(v * 2.885390081777927f));
    float r; asm("rcp.approx.f32 %0, %1;" : "=f"(r) : "f"(1.0f + e));
    return 1.0f - 2.0f * r;
}

// ---------------- merged pre-pass (natural channel order) ----------------
__global__ __launch_bounds__(256) void pack_all(
    const float* __restrict__ x, const float* __restrict__ hs,
    const float* wxi, const float* wxf, const float* wxo, const float* wxg,
    const float* whi, const float* whf, const float* who, const float* whg,
    const float* bxi, const float* bxf, const float* bxo, const float* bxg,
    const float* bhi, const float* bhf, const float* bho, const float* bhg) {
    const int blk = blockIdx.x;
    const int t = threadIdx.x;
    if (blk < 2048) {
        __shared__ float sm[CTOT * 65];
        int b = blk >> 6, y = blk & 63;
        #pragma unroll
        for (int i = 0; i < 6; i++) {
            int u = t + i * 256;
            int c = u >> 4, x4 = (u & 15) * 4;
            const float* src = (c < CIN)
                ? x  + ((size_t)(b * CIN + c) * HH + y) * WW + x4
                : hs + ((size_t)(b * HCC + (c - CIN)) * HH + y) * WW + x4;
            float4 v = *(const float4*)src;
            float* d = sm + c * 65 + x4;
            d[0] = v.x; d[1] = v.y; d[2] = v.z; d[3] = v.w;
        }
        __syncthreads();
        __half* dst = g_A + (size_t)(b * HH + y) * WW * CTOT;
        int o = t, xp = t / 96, cpos = t - xp * 96;
        #pragma unroll
        for (int k = 0; k < 24; k++) {
            dst[o] = __float2half_rn(sm[cpos * 65 + xp]);
            o += 256; cpos += 64; xp += 2;
            if (cpos >= 96) { cpos -= 96; xp += 1; }
        }
    } else if (blk < 2912) {
        const float* wx[4] = {wxi, wxf, wxo, wxg};
        const float* wh[4] = {whi, whf, who, whg};
        int g = (blk - 2048) * 256 + t;
        int ci = g & 31;
        int r = g >> 5;
        int n = r & 255;
        int tk = r >> 8;
        int tap = tk / 3, kc = tk - 3 * tap;
        int ky = tap / 3, kx = tap - 3 * ky;
        int hc = n >> 2, gate = n & 3;
        int cg = kc * 32 + ci;
        float v;
        if (cg < CIN) v = wx[gate][((hc * CIN + cg) * 3 + ky) * 3 + kx];
        else          v = wh[gate][((hc * HCC + (cg - CIN)) * 3 + ky) * 3 + kx];
        g_W[g] = __float2half_rn(v);
    } else {
        const float* bx[4] = {bxi, bxf, bxo, bxg};
        const float* bh[4] = {bhi, bhf, bho, bhg};
        int hc = t >> 2, gate = t & 3;
        g_bias[t] = bx[gate][hc] + bh[gate][hc];
    }
}

// ---------------- main kernel ----------------
#define ROWB 80                                 // padded row stride (bytes)
#define AREG_B   (4 * 66 * ROWB)                // 21120 bytes per kc region
#define A_TOTAL  (3 * AREG_B)                   // 63360
#define B_STAGE_B (128 * ROWB)                  // 10240
#define SMEM_BYTES (A_TOTAL + 3 * B_STAGE_B)    // 94080 -> 2 CTAs/SM

__global__ __launch_bounds__(256, 2) void convlstm_mma(
    const float* __restrict__ cs, float* __restrict__ hout, float* __restrict__ cout) {
    extern __shared__ __half smh[];
    const uint32_t sb = smem_u32(smh);
    const int tid  = threadIdx.x;
    const int lane = tid & 31;
    const int wid  = tid >> 5;
    const int gid  = lane >> 2;
    const int tig  = lane & 3;
    const int warp_m = (wid >> 2) * 64;        // 2 warps over M (128)
    const int warpY  = warp_m >> 6;
    const int warp_n = (wid & 3) * 32;         // 4 warps over N (128)

    const int bx = blockIdx.x;
    const int nb = bx & 1;                     // N-half: hc [nb*32, nb*32+32)
    const int b  = bx >> 6;
    const int y0 = ((bx >> 1) & 31) * 2;
    const __half* Ab = g_A + (size_t)b * HH * WW * CTOT;

    // ldmatrix lane address offsets (bytes)
    // A x4: q=lane>>3 -> mat [m(q&1)*8, k(q>>1)*8]; row in mat = lane&7
    const uint32_t laneA = (uint32_t)(((lane & 7) + ((lane >> 3) & 1) * 8) * ROWB
                                      + (lane >> 4) * 16);
    // B x4: q -> mat [n(q>>1)*8, k(q&1)*8]; row = lane&7
    const uint32_t laneB = (uint32_t)((((lane >> 4) * 8) + (lane & 7)) * ROWB
                                      + ((lane >> 3) & 1) * 16);

    float acc[4][4][4];
    #pragma unroll
    for (int mi = 0; mi < 4; mi++)
        #pragma unroll
        for (int ni = 0; ni < 4; ni++)
            #pragma unroll
            for (int q = 0; q < 4; q++) acc[mi][ni][q] = 0.0f;

    auto prefetchB = [&](int it, int s) {
        const __half* Wsrc = g_W + (size_t)it * (NGATE * 32) + nb * (128 * 32);
        const uint32_t bb = sb + A_TOTAL + (uint32_t)s * B_STAGE_B;
        #pragma unroll
        for (int u = 0; u < 2; u++) {
            int c = tid + u * 256;             // 0..511
            int r = c >> 2, j = c & 3;         // r 0..127
            cp_async16(bb + (uint32_t)(r * ROWB + j * 16), Wsrc + r * 32 + j * 8, 16u);
        }
        CP_COMMIT();
    };

    // A-resident fill: 3 kc regions x 4 rows x 66 cols x 64B data (3168 x 16B)
    for (int i = tid; i < 3168; i += 256) {
        int j = i & 3;
        int rest = i >> 2;
        int xx = rest % 66;
        int r2 = rest / 66;
        int yy = r2 & 3, kc = r2 >> 2;
        int gy = y0 + yy - 1, gx = xx - 1;
        bool ok = ((unsigned)gy < HH) && ((unsigned)gx < WW);
        const __half* src = ok ? (Ab + ((size_t)(gy * WW + gx)) * CTOT + kc * 32 + j * 8)
                               : Ab;
        cp_async16(sb + (uint32_t)(kc * AREG_B + (yy * 66 + xx) * ROWB + j * 16),
                   src, ok ? 16u : 0u);
    }
    CP_COMMIT();
    prefetchB(0, 0);
    prefetchB(1, 1);

    int kc = 0, ky = 0, kx = 0;
    for (int it = 0; it < NITER; it++) {
        if (it + 1 < NITER) { CP_WAIT(1); } else { CP_WAIT(0); }
        __syncthreads();
        if (it + 2 < NITER) prefetchB(it + 2, (it + 2) % 3);
        const int s = it % 3;

        const uint32_t aBase = sb + (uint32_t)(kc * AREG_B + ((warpY + ky) * 66 + kx) * ROWB)
                             + laneA;
        const uint32_t bBase = sb + A_TOTAL + (uint32_t)(s * B_STAGE_B + warp_n * ROWB)
                             + laneB;

        #pragma unroll
        for (int kh = 0; kh < 2; kh++) {
            const uint32_t kb = (uint32_t)(kh * 32);   // k16 step = 32 bytes
            uint32_t a[4][4];
            #pragma unroll
            for (int mi = 0; mi < 4; mi++)
                ldm4(a[mi], aBase + (uint32_t)(mi * 16 * ROWB) + kb);
            uint32_t b01[4], b23[4];
            ldm4(b01, bBase + kb);
            ldm4(b23, bBase + (uint32_t)(16 * ROWB) + kb);

            #pragma unroll
            for (int mi = 0; mi < 4; mi++) {
                mma_f16(acc[mi][0], a[mi][0], a[mi][1], a[mi][2], a[mi][3], b01[0], b01[1]);
                mma_f16(acc[mi][1], a[mi][0], a[mi][1], a[mi][2], a[mi][3], b01[2], b01[3]);
                mma_f16(acc[mi][2], a[mi][0], a[mi][1], a[mi][2], a[mi][3], b23[0], b23[1]);
                mma_f16(acc[mi][3], a[mi][0], a[mi][1], a[mi][2], a[mi][3], b23[2], b23[3]);
            }
        }

        if (++kc == 3) { kc = 0; if (++kx == 3) { kx = 0; ky++; } }
    }

    // ---- fused LSTM epilogue ----
    const int odd = tig & 1;
    #pragma unroll
    for (int mi = 0; mi < 4; mi++) {
        #pragma unroll
        for (int ni = 0; ni < 4; ni++) {
            float c0 = acc[mi][ni][0], c1 = acc[mi][ni][1];
            float c2 = acc[mi][ni][2], c3 = acc[mi][ni][3];
            float e0 = __shfl_xor_sync(0xFFFFFFFFu, odd ? c0 : c2, 1);
            float e1 = __shfl_xor_sync(0xFFFFFFFFu, odd ? c1 : c3, 1);
            float zi, zf, zo, zg;
            int row;
            if (!odd) { zi = c0; zf = c1; zo = e0; zg = e1; row = warp_m + mi * 16 + gid; }
            else      { zi = e0; zf = e1; zo = c2; zg = c3; row = warp_m + mi * 16 + gid + 8; }
            const int hc = nb * 32 + (warp_n >> 2) + ni * 2 + (tig >> 1);
            const float4 bv = *(const float4*)(g_bias + hc * 4);
            zi += bv.x; zf += bv.y; zo += bv.z; zg += bv.w;
            float ig = fsigmoid(zi), fg = fsigmoid(zf), og = fsigmoid(zo);
            float gg = ftanh(zg);
            const int y = y0 + (row >> 6);
            const int x = row & 63;
            size_t cidx = ((size_t)(b * HCC + hc) * HH + y) * WW + x;
            float cn = fg * cs[cidx] + ig * gg;
            hout[cidx] = og * ftanh(cn);
            cout[cidx] = cn;
        }
    }
}

// ---------------- host ----------------
extern "C" void kernel_launch(void* const* d_in, const int* in_sizes, int n_in,
                              void* d_out, int out_size) {
    const float* x  = (const float*)d_in[0];
    const float* hs = (const float*)d_in[1];
    const float* cs = (const float*)d_in[2];

    const float *WX[4], *BX[4], *WH[4], *BH[4];
    if (in_sizes[4] == HCC) {
        for (int g = 0; g < 4; g++) {
            WX[g] = (const float*)d_in[3 + 2 * g];
            BX[g] = (const float*)d_in[4 + 2 * g];
            WH[g] = (const float*)d_in[11 + 2 * g];
            BH[g] = (const float*)d_in[12 + 2 * g];
        }
    } else {
        for (int g = 0; g < 4; g++) {
            WX[g] = (const float*)d_in[3 + g];
            BX[g] = (const float*)d_in[7 + g];
            WH[g] = (const float*)d_in[11 + g];
            BH[g] = (const float*)d_in[15 + g];
        }
    }

    float* hout = (float*)d_out;
    float* cout = hout + (size_t)BB * HCC * HH * WW;

    pack_all<<<2913, 256>>>(x, hs,
        WX[0], WX[1], WX[2], WX[3], WH[0], WH[1], WH[2], WH[3],
        BX[0], BX[1], BX[2], BX[3], BH[0], BH[1], BH[2], BH[3]);

    cudaFuncSetAttribute(convlstm_mma, cudaFuncAttributeMaxDynamicSharedMemorySize, SMEM_BYTES);
    convlstm_mma<<<2048, 256, SMEM_BYTES>>>(cs, hout, cout);
}

// round 10
// speedup vs baseline: 8.2657x; 1.0863x over previous
#include <cuda_runtime.h>
#include <cuda_fp16.h>
#include <cstdint>

#define BB   32
#define CIN  32
#define HCC  64
#define HH   64
#define WW   64
#define CTOT 96
#define NGATE 256        // n = hc*4 + gate
#define NITER 27

// ---------------- device scratch ----------------
__device__ __half g_A[(size_t)BB * HH * WW * CTOT];  // [b][y][x][c] natural order fp16
__device__ __half g_W[NITER * NGATE * 32];           // [tap*3+kc][hc*4+gate][ci]
__device__ float  g_bias[NGATE];

__device__ __forceinline__ void cp_async16(uint32_t dst, const void* src, uint32_t sz) {
    asm volatile("cp.async.cg.shared.global [%0], [%1], 16, %2;"
                 :: "r"(dst), "l"(src), "r"(sz) : "memory");
}
__device__ __forceinline__ uint32_t smem_u32(const void* p) {
    uint32_t a;
    asm("{ .reg .u64 t; cvta.to.shared.u64 t, %1; cvt.u32.u64 %0, t; }" : "=r"(a) : "l"(p));
    return a;
}
#define CP_COMMIT() asm volatile("cp.async.commit_group;" ::: "memory")
#define CP_WAIT(n)  asm volatile("cp.async.wait_group %0;" :: "n"(n) : "memory")

__device__ __forceinline__ void ldm4(uint32_t* r, uint32_t addr) {
    asm volatile("ldmatrix.sync.aligned.m8n8.x4.shared.b16 {%0,%1,%2,%3}, [%4];"
                 : "=r"(r[0]), "=r"(r[1]), "=r"(r[2]), "=r"(r[3]) : "r"(addr));
}
__device__ __forceinline__ void mma_f16(float* d, uint32_t a0, uint32_t a1, uint32_t a2,
                                        uint32_t a3, uint32_t b0, uint32_t b1) {
    asm volatile(
        "mma.sync.aligned.m16n8k16.row.col.f32.f16.f16.f32 "
        "{%0,%1,%2,%3}, {%4,%5,%6,%7}, {%8,%9}, {%0,%1,%2,%3};"
        : "+f"(d[0]), "+f"(d[1]), "+f"(d[2]), "+f"(d[3])
        : "r"(a0), "r"(a1), "r"(a2), "r"(a3), "r"(b0), "r"(b1));
}
__device__ __forceinline__ float fsigmoid(float v) {
    float e; asm("ex2.approx.f32 %0, %1;" : "=f"(e) : "f"(-v * 1.4426950408889634f));
    float r; asm("rcp.approx.f32 %0, %1;" : "=f"(r) : "f"(1.0f + e));
    return r;
}
__device__ __forceinline__ float ftanh(float v) {
    float e; asm("ex2.approx.f32 %0, %1;" : "=f"(e) : "f"(v * 2.885390081777927f));
    float r; asm("rcp.approx.f32 %0, %1;" : "=f"(r) : "f"(1.0f + e));
    return 1.0f - 2.0f * r;
}

// ---------------- merged pre-pass (natural channel order) ----------------
__global__ __launch_bounds__(256) void pack_all(
    const float* __restrict__ x, const float* __restrict__ hs,
    const float* wxi, const float* wxf, const float* wxo, const float* wxg,
    const float* whi, const float* whf, const float* who, const float* whg,
    const float* bxi, const float* bxf, const float* bxo, const float* bxg,
    const float* bhi, const float* bhf, const float* bho, const float* bhg) {
    const int blk = blockIdx.x;
    const int t = threadIdx.x;
    if (blk < 2048) {
        __shared__ float sm[CTOT * 65];
        int b = blk >> 6, y = blk & 63;
        #pragma unroll
        for (int i = 0; i < 6; i++) {
            int u = t + i * 256;
            int c = u >> 4, x4 = (u & 15) * 4;
            const float* src = (c < CIN)
                ? x  + ((size_t)(b * CIN + c) * HH + y) * WW + x4
                : hs + ((size_t)(b * HCC + (c - CIN)) * HH + y) * WW + x4;
            float4 v = *(const float4*)src;
            float* d = sm + c * 65 + x4;
            d[0] = v.x; d[1] = v.y; d[2] = v.z; d[3] = v.w;
        }
        __syncthreads();
        __half* dst = g_A + (size_t)(b * HH + y) * WW * CTOT;
        int o = t, xp = t / 96, cpos = t - xp * 96;
        #pragma unroll
        for (int k = 0; k < 24; k++) {
            dst[o] = __float2half_rn(sm[cpos * 65 + xp]);
            o += 256; cpos += 64; xp += 2;
            if (cpos >= 96) { cpos -= 96; xp += 1; }
        }
    } else if (blk < 2912) {
        const float* wx[4] = {wxi, wxf, wxo, wxg};
        const float* wh[4] = {whi, whf, who, whg};
        int g = (blk - 2048) * 256 + t;
        int ci = g & 31;
        int r = g >> 5;
        int n = r & 255;
        int tk = r >> 8;
        int tap = tk / 3, kc = tk - 3 * tap;
        int ky = tap / 3, kx = tap - 3 * ky;
        int hc = n >> 2, gate = n & 3;
        int cg = kc * 32 + ci;
        float v;
        if (cg < CIN) v = wx[gate][((hc * CIN + cg) * 3 + ky) * 3 + kx];
        else          v = wh[gate][((hc * HCC + (cg - CIN)) * 3 + ky) * 3 + kx];
        g_W[g] = __float2half_rn(v);
    } else {
        const float* bx[4] = {bxi, bxf, bxo, bxg};
        const float* bh[4] = {bhi, bhf, bho, bhg};
        int hc = t >> 2, gate = t & 3;
        g_bias[t] = bx[gate][hc] + bh[gate][hc];
    }
}

// ---------------- main kernel ----------------
#define AROWB 208                               // A row stride: 96ch*2B + 16B pad
#define A_TOTAL (4 * 66 * AROWB)                // 54912
#define BROWB 80
#define B_STAGE_B (128 * BROWB)                 // 10240
#define SMEM_BYTES (A_TOTAL + 4 * B_STAGE_B)    // 95872 -> 2 CTAs/SM

__global__ __launch_bounds__(256, 2) void convlstm_mma(
    const float* __restrict__ cs, float* __restrict__ hout, float* __restrict__ cout) {
    extern __shared__ __half smh[];
    const uint32_t sb = smem_u32(smh);
    const int tid  = threadIdx.x;
    const int lane = tid & 31;
    const int wid  = tid >> 5;
    const int gid  = lane >> 2;
    const int tig  = lane & 3;
    const int warp_m = (wid >> 2) * 64;        // 2 warps over M (128)
    const int warpY  = warp_m >> 6;
    const int warp_n = (wid & 3) * 32;         // 4 warps over N (128)

    const int bx = blockIdx.x;
    const int nb = bx & 1;                     // N-half: hc [nb*32, nb*32+32)
    const int b  = bx >> 6;
    const int y0 = ((bx >> 1) & 31) * 2;
    const __half* Ab = g_A + (size_t)b * HH * WW * CTOT;

    // ldmatrix lane address offsets (bytes)
    const uint32_t laneA = (uint32_t)(((lane & 7) + ((lane >> 3) & 1) * 8) * AROWB
                                      + (lane >> 4) * 16);
    const uint32_t laneB = (uint32_t)((((lane >> 4) * 8) + (lane & 7)) * BROWB
                                      + ((lane >> 3) & 1) * 16);

    float acc[4][4][4];
    #pragma unroll
    for (int mi = 0; mi < 4; mi++)
        #pragma unroll
        for (int ni = 0; ni < 4; ni++)
            #pragma unroll
            for (int q = 0; q < 4; q++) acc[mi][ni][q] = 0.0f;

    auto prefetchB = [&](int it, int s) {
        const __half* Wsrc = g_W + (size_t)it * (NGATE * 32) + nb * (128 * 32);
        const uint32_t bb = sb + A_TOTAL + (uint32_t)s * B_STAGE_B;
        #pragma unroll
        for (int u = 0; u < 2; u++) {
            int c = tid + u * 256;             // 0..511
            int r = c >> 2, j = c & 3;         // r 0..127
            cp_async16(bb + (uint32_t)(r * BROWB + j * 16), Wsrc + r * 32 + j * 8, 16u);
        }
        CP_COMMIT();
    };

    // A-resident fill: 4 rows x 66 cols x 96 ch (12 chunks of 16B per pixel)
    for (int i = tid; i < 3168; i += 256) {
        int j = i % 12;
        int rest = i / 12;                     // 0..263
        int xx = rest % 66;
        int yy = rest / 66;                    // 0..3
        int gy = y0 + yy - 1, gx = xx - 1;
        bool ok = ((unsigned)gy < HH) && ((unsigned)gx < WW);
        const __half* src = ok ? (Ab + ((size_t)(gy * WW + gx)) * CTOT + j * 8) : Ab;
        cp_async16(sb + (uint32_t)((yy * 66 + xx) * AROWB + j * 16), src, ok ? 16u : 0u);
    }
    CP_COMMIT();
    prefetchB(0, 0);
    prefetchB(1, 1);

    int kc = 0, ky = 0, kx = 0;
    for (int it = 0; it < NITER; it++) {
        if ((it & 1) == 0) {
            CP_WAIT(0);                 // drain own groups (publishes P(it),P(it+1))
            __syncthreads();            // cross-thread visibility for both stages
            if (it + 2 < NITER) prefetchB(it + 2, (it + 2) & 3);
        } else {
            if (it + 2 < NITER) prefetchB(it + 2, (it + 2) & 3);
        }
        const int s = it & 3;

        const uint32_t aBase = sb + (uint32_t)(((warpY + ky) * 66 + kx) * AROWB + kc * 64)
                             + laneA;
        const uint32_t bBase = sb + A_TOTAL + (uint32_t)(s * B_STAGE_B + warp_n * BROWB)
                             + laneB;

        #pragma unroll
        for (int kh = 0; kh < 2; kh++) {
            const uint32_t kb = (uint32_t)(kh * 32);   // k16 step = 32 bytes
            uint32_t a[4][4];
            #pragma unroll
            for (int mi = 0; mi < 4; mi++)
                ldm4(a[mi], aBase + (uint32_t)(mi * 16 * AROWB) + kb);
            uint32_t b01[4], b23[4];
            ldm4(b01, bBase + kb);
            ldm4(b23, bBase + (uint32_t)(16 * BROWB) + kb);

            #pragma unroll
            for (int mi = 0; mi < 4; mi++) {
                mma_f16(acc[mi][0], a[mi][0], a[mi][1], a[mi][2], a[mi][3], b01[0], b01[1]);
                mma_f16(acc[mi][1], a[mi][0], a[mi][1], a[mi][2], a[mi][3], b01[2], b01[3]);
                mma_f16(acc[mi][2], a[mi][0], a[mi][1], a[mi][2], a[mi][3], b23[0], b23[1]);
                mma_f16(acc[mi][3], a[mi][0], a[mi][1], a[mi][2], a[mi][3], b23[2], b23[3]);
            }
        }

        if (++kc == 3) { kc = 0; if (++kx == 3) { kx = 0; ky++; } }
    }

    // ---- fused LSTM epilogue (cs loads batched per mi-row) ----
    const int odd = tig & 1;
    #pragma unroll
    for (int mi = 0; mi < 4; mi++) {
        const int rowE = warp_m + mi * 16 + gid;          // even-lane row
        const int row  = odd ? rowE + 8 : rowE;
        const int y = y0 + (row >> 6);
        const int x = row & 63;
        // batch the 4 cell-state loads for this mi
        int  cidx[4];
        float csv[4];
        #pragma unroll
        for (int ni = 0; ni < 4; ni++) {
            const int hc = nb * 32 + (warp_n >> 2) + ni * 2 + (tig >> 1);
            cidx[ni] = ((b * HCC + hc) * HH + y) * WW + x;
            csv[ni] = cs[cidx[ni]];
        }
        #pragma unroll
        for (int ni = 0; ni < 4; ni++) {
            float c0 = acc[mi][ni][0], c1 = acc[mi][ni][1];
            float c2 = acc[mi][ni][2], c3 = acc[mi][ni][3];
            float e0 = __shfl_xor_sync(0xFFFFFFFFu, odd ? c0 : c2, 1);
            float e1 = __shfl_xor_sync(0xFFFFFFFFu, odd ? c1 : c3, 1);
            float zi, zf, zo, zg;
            if (!odd) { zi = c0; zf = c1; zo = e0; zg = e1; }
            else      { zi = e0; zf = e1; zo = c2; zg = c3; }
            const int hc = nb * 32 + (warp_n >> 2) + ni * 2 + (tig >> 1);
            const float4 bv = *(const float4*)(g_bias + hc * 4);
            zi += bv.x; zf += bv.y; zo += bv.z; zg += bv.w;
            float ig = fsigmoid(zi), fg = fsigmoid(zf), og = fsigmoid(zo);
            float gg = ftanh(zg);
            float cn = fg * csv[ni] + ig * gg;
            hout[cidx[ni]] = og * ftanh(cn);
            cout[cidx[ni]] = cn;
        }
    }
}

// ---------------- host ----------------
extern "C" void kernel_launch(void* const* d_in, const int* in_sizes, int n_in,
                              void* d_out, int out_size) {
    const float* x  = (const float*)d_in[0];
    const float* hs = (const float*)d_in[1];
    const float* cs = (const float*)d_in[2];

    const float *WX[4], *BX[4], *WH[4], *BH[4];
    if (in_sizes[4] == HCC) {
        for (int g = 0; g < 4; g++) {
            WX[g] = (const float*)d_in[3 + 2 * g];
            BX[g] = (const float*)d_in[4 + 2 * g];
            WH[g] = (const float*)d_in[11 + 2 * g];
            BH[g] = (const float*)d_in[12 + 2 * g];
        }
    } else {
        for (int g = 0; g < 4; g++) {
            WX[g] = (const float*)d_in[3 + g];
            BX[g] = (const float*)d_in[7 + g];
            WH[g] = (const float*)d_in[11 + g];
            BH[g] = (const float*)d_in[15 + g];
        }
    }

    float* hout = (float*)d_out;
    float* cout = hout + (size_t)BB * HCC * HH * WW;

    pack_all<<<2913, 256>>>(x, hs,
        WX[0], WX[1], WX[2], WX[3], WH[0], WH[1], WH[2], WH[3],
        BX[0], BX[1], BX[2], BX[3], BH[0], BH[1], BH[2], BH[3]);

    cudaFuncSetAttribute(convlstm_mma, cudaFuncAttributeMaxDynamicSharedMemorySize, SMEM_BYTES);
    convlstm_mma<<<2048, 256, SMEM_BYTES>>>(cs, hout, cout);
}